// round 11
// baseline (speedup 1.0000x reference)
#include <cuda_runtime.h>
#include <math.h>

// Problem constants
#define NN 20000      // nodes
#define DF 256        // feature dim = H*D
#define PM 3          // metapaths
#define EE 60000      // edges per metapath
#define LL 4          // seq len
#define HH 8          // heads
#define DD 32         // head dim
#define G3 768        // 3 * DF (gate dim)

// ---------------- scratch (device globals; no allocation) ----------------
__device__ float g_ft  [(size_t)NN * DF];            // normalized node features
__device__ float g_gi  [(size_t)PM * NN * G3];       // per-node input gates (+b_ih)
__device__ float g_h   [(size_t)PM * EE * DF];       // GRU hidden per edge
__device__ float g_gh  [(size_t)PM * EE * G3];       // hidden gates (+b_hh)
__device__ float g_hout[(size_t)PM * NN * DF];       // per-metapath aggregated output
__device__ float g_s   [PM];
__device__ float g_beta[PM];

__device__ __forceinline__ float sigmoidf_(float x) {
    return 1.0f / (1.0f + expf(-x));
}

// ---------------- zero scratch that gets accumulated into ----------------
__global__ void zero_kernel() {
    size_t i = (size_t)blockIdx.x * blockDim.x + threadIdx.x;
    size_t total = (size_t)PM * NN * DF;
    if (i < total) g_hout[i] = 0.0f;
    if (i < PM) g_s[i] = 0.0f;
}

// ---------------- ft = l2norm over heads (axis=1 of [N,H,D]) ----------------
__global__ void ft_norm_kernel(const float* __restrict__ feat) {
    int t = blockIdx.x * blockDim.x + threadIdx.x;   // over N*DD
    if (t >= NN * DD) return;
    int n = t / DD, d = t % DD;
    const float* f = feat + (size_t)n * DF + d;
    float v[HH];
    float s = 0.0f;
#pragma unroll
    for (int h = 0; h < HH; h++) { v[h] = f[h * DD]; s += v[h] * v[h]; }
    float inv = 1.0f / fmaxf(sqrtf(s), 1e-12f);
    float* o = g_ft + (size_t)n * DF + d;
#pragma unroll
    for (int h = 0; h < HH; h++) o[h * DD] = v[h] * inv;
}

// ---------------- SGEMM (NT): C[M,768] = A[M,256] @ B[768,256]^T + bias ----------------
// grouped over blockIdx.z = metapath p
#define BM 128
#define BN 64
#define BK 16

__global__ __launch_bounds__(256) void sgemm_nt_bias(
    const float* __restrict__ Abase, size_t aPstride,
    const float* __restrict__ Bbase,          // [p][768][256]
    const float* __restrict__ biasBase,       // [p][768]
    float* __restrict__ Cbase, size_t cPstride,
    int M)
{
    int p = blockIdx.z;
    const float* A    = Abase    + (size_t)p * aPstride;
    const float* B    = Bbase    + (size_t)p * G3 * DF;
    const float* bias = biasBase + (size_t)p * G3;
    float* C          = Cbase    + (size_t)p * cPstride;

    __shared__ __align__(16) float As[BK][BM];
    __shared__ __align__(16) float Bs[BK][BN];

    int tid = threadIdx.x;
    int ty = tid >> 4;        // 0..15 -> 8 rows each
    int tx = tid & 15;        // 0..15 -> 4 cols each
    int rowBase = blockIdx.x * BM;
    int colBase = blockIdx.y * BN;

    float acc[8][4];
#pragma unroll
    for (int i = 0; i < 8; i++)
#pragma unroll
        for (int j = 0; j < 4; j++) acc[i][j] = 0.0f;

    int ldRow = tid >> 2;            // 0..63
    int ldK4  = (tid & 3) << 2;      // 0,4,8,12

    for (int k0 = 0; k0 < DF; k0 += BK) {
        // A tile: 128x16, two passes of 64 rows
#pragma unroll
        for (int pass = 0; pass < 2; pass++) {
            int r = rowBase + ldRow + pass * 64;
            float4 av = make_float4(0.f, 0.f, 0.f, 0.f);
            if (r < M) av = *(const float4*)(A + (size_t)r * DF + k0 + ldK4);
            As[ldK4 + 0][ldRow + pass * 64] = av.x;
            As[ldK4 + 1][ldRow + pass * 64] = av.y;
            As[ldK4 + 2][ldRow + pass * 64] = av.z;
            As[ldK4 + 3][ldRow + pass * 64] = av.w;
        }
        // B tile: 64x16
        {
            int r = colBase + ldRow;
            float4 bv = *(const float4*)(B + (size_t)r * DF + k0 + ldK4);
            Bs[ldK4 + 0][ldRow] = bv.x;
            Bs[ldK4 + 1][ldRow] = bv.y;
            Bs[ldK4 + 2][ldRow] = bv.z;
            Bs[ldK4 + 3][ldRow] = bv.w;
        }
        __syncthreads();

#pragma unroll
        for (int kk = 0; kk < BK; kk++) {
            float4 a0 = *(const float4*)&As[kk][ty * 8];
            float4 a1 = *(const float4*)&As[kk][ty * 8 + 4];
            float4 b0 = *(const float4*)&Bs[kk][tx * 4];
            float a[8] = {a0.x, a0.y, a0.z, a0.w, a1.x, a1.y, a1.z, a1.w};
            float b[4] = {b0.x, b0.y, b0.z, b0.w};
#pragma unroll
            for (int i = 0; i < 8; i++)
#pragma unroll
                for (int j = 0; j < 4; j++) acc[i][j] += a[i] * b[j];
        }
        __syncthreads();
    }

    int col = colBase + tx * 4;
    float4 bv = *(const float4*)(bias + col);
#pragma unroll
    for (int i = 0; i < 8; i++) {
        int row = rowBase + ty * 8 + i;
        if (row < M) {
            float4 o;
            o.x = acc[i][0] + bv.x;
            o.y = acc[i][1] + bv.y;
            o.z = acc[i][2] + bv.z;
            o.w = acc[i][3] + bv.w;
            *(float4*)(C + (size_t)row * G3 + col) = o;
        }
    }
}

// ---------------- GRU step 0 (h=0 so gh = b_hh) ----------------
__global__ void gru_step0(const int* __restrict__ emi, const float* __restrict__ b_hh) {
    size_t i = (size_t)blockIdx.x * blockDim.x + threadIdx.x;
    size_t total = (size_t)PM * EE * DF;
    if (i >= total) return;
    int k = (int)(i & 255);
    size_t pe = i >> 8;                    // p*EE + e
    int p = (int)(pe / EE);
    int node = emi[pe * LL + 0];
    const float* gi = g_gi + ((size_t)p * NN + node) * G3;
    const float* bh = b_hh + (size_t)p * G3;
    float r  = sigmoidf_(gi[k]       + bh[k]);
    float z  = sigmoidf_(gi[k + 256] + bh[k + 256]);
    float nv = tanhf(gi[k + 512] + r * bh[k + 512]);
    g_h[i] = (1.0f - z) * nv;
}

// ---------------- GRU step l (l = 1..3); g_gh already contains +b_hh ----------------
__global__ void gru_step(const int* __restrict__ emi, int l) {
    size_t i = (size_t)blockIdx.x * blockDim.x + threadIdx.x;
    size_t total = (size_t)PM * EE * DF;
    if (i >= total) return;
    int k = (int)(i & 255);
    size_t pe = i >> 8;
    int p = (int)(pe / EE);
    int node = emi[pe * LL + l];
    const float* gi = g_gi + ((size_t)p * NN + node) * G3;
    const float* gh = g_gh + pe * G3;
    float r  = sigmoidf_(gi[k]       + gh[k]);
    float z  = sigmoidf_(gi[k + 256] + gh[k + 256]);
    float nv = tanhf(gi[k + 512] + r * gh[k + 512]);
    float hp = g_h[i];
    g_h[i] = (1.0f - z) * nv + z * hp;
}

// ---------------- edge attention + segment sum ----------------
// one block (256 thr) per (p, e). Thread k -> head h = k/32, dim d = k%32.
__global__ __launch_bounds__(256) void edge_attn_kernel(const int* __restrict__ edst) {
    int pe = blockIdx.x;                   // p*EE + e
    int p = pe / EE;
    int k = threadIdx.x;
    int h = k >> 5, d = k & 31;

    float v = g_h[(size_t)pe * DF + k];

    __shared__ float sv[DF];
    __shared__ float snorm[DD];
    __shared__ float ssim[HH];

    sv[k] = v * v;
    __syncthreads();
    if (k < DD) {
        float s = 0.0f;
#pragma unroll
        for (int hh = 0; hh < HH; hh++) s += sv[hh * DD + k];
        snorm[k] = fmaxf(sqrtf(s), 1e-12f);
    }
    __syncthreads();

    float eft = v / snorm[d];

    int dst = edst[pe];
    float ftv = g_ft[(size_t)dst * DF + k];
    float prod = eft * ftv;
    // reduce over the 32 lanes of this warp (= one head)
#pragma unroll
    for (int off = 16; off > 0; off >>= 1)
        prod += __shfl_down_sync(0xFFFFFFFFu, prod, off);
    if ((k & 31) == 0) ssim[h] = prod;
    __syncthreads();

    // softmax over 8 heads (each thread computes it locally; cheap)
    float mx = ssim[0];
#pragma unroll
    for (int i = 1; i < HH; i++) mx = fmaxf(mx, ssim[i]);
    float den = 0.0f;
#pragma unroll
    for (int i = 0; i < HH; i++) den += expf(ssim[i] - mx);
    float a = expf(ssim[h] - mx) / den;

    atomicAdd(&g_hout[((size_t)p * NN + dst) * DF + k], eft * a);
}

// ---------------- semantic attention scores ----------------
__global__ __launch_bounds__(256) void semantic_kernel(const float* __restrict__ fc1,
                                                       const float* __restrict__ fc2) {
    __shared__ float s1[DD * DD];   // fc1_w [32,32]
    __shared__ float s2[HH * DD];   // fc2   [8,32]
    __shared__ float red[256];
    int tid = threadIdx.x;
    for (int i = tid; i < DD * DD; i += 256) s1[i] = fc1[i];
    if (tid < HH * DD) s2[tid] = fc2[tid];
    __syncthreads();

    int g = blockIdx.x * 256 + tid;   // over PM*NN*HH = 480000
    int h = g % HH;
    int pn = g / HH;                  // p*NN + n
    const float* hvp = g_hout + (size_t)pn * DF + h * DD;
    float hv[DD];
#pragma unroll
    for (int i = 0; i < 8; i++) {
        float4 v4 = *(const float4*)(hvp + i * 4);
        hv[i * 4 + 0] = v4.x; hv[i * 4 + 1] = v4.y;
        hv[i * 4 + 2] = v4.z; hv[i * 4 + 3] = v4.w;
    }
    float acc = 0.0f;
    for (int e = 0; e < DD; e++) {
        float s = 0.0f;
#pragma unroll
        for (int d = 0; d < DD; d++) s += hv[d] * s1[e * DD + d];
        acc += tanhf(s) * s2[h * DD + e];
    }

    red[tid] = acc;
    __syncthreads();
    for (int s = 128; s > 0; s >>= 1) {
        if (tid < s) red[tid] += red[tid + s];
        __syncthreads();
    }
    if (tid == 0) {
        int p = (blockIdx.x * 256) / (NN * HH);   // blocks never straddle p (160000 % 256 == 0)
        atomicAdd(&g_s[p], red[0]);
    }
}

// ---------------- beta = softmax(mean scores) ----------------
__global__ void beta_kernel() {
    if (threadIdx.x == 0 && blockIdx.x == 0) {
        float s[PM];
        float mx = -1e30f;
#pragma unroll
        for (int p = 0; p < PM; p++) { s[p] = g_s[p] / (float)NN; mx = fmaxf(mx, s[p]); }
        float den = 0.0f;
#pragma unroll
        for (int p = 0; p < PM; p++) { s[p] = expf(s[p] - mx); den += s[p]; }
#pragma unroll
        for (int p = 0; p < PM; p++) g_beta[p] = s[p] / den;
    }
}

// ---------------- final mix ----------------
__global__ void output_kernel(float* __restrict__ out) {
    size_t i = (size_t)blockIdx.x * blockDim.x + threadIdx.x;
    const size_t total = (size_t)NN * DF;
    if (i >= total) return;
    out[i] = g_beta[0] * g_hout[i]
           + g_beta[1] * g_hout[total + i]
           + g_beta[2] * g_hout[2 * total + i];
}

// ---------------- launch ----------------
extern "C" void kernel_launch(void* const* d_in, const int* in_sizes, int n_in,
                              void* d_out, int out_size) {
    // -------- bind inputs by SIZE (robust to metadata ordering) --------
    int idx_feat = -1, idx_fc1 = -1, idx_fc2 = -1, idx_emi = -1, idx_edst = -1;
    int idx_wA = -1, idx_wB = -1, idx_bA = -1, idx_bB = -1;
    for (int i = 0; i < n_in; i++) {
        int s = in_sizes[i];
        if      (s == NN * DF)           idx_feat = i;
        else if (s == PM * G3 * DF)      { if (idx_wA < 0) idx_wA = i; else idx_wB = i; }
        else if (s == PM * G3)           { if (idx_bA < 0) idx_bA = i; else idx_bB = i; }
        else if (s == DD * DD)           idx_fc1 = i;
        else if (s == HH * DD)           idx_fc2 = i;
        else if (s == PM * EE * LL)      idx_emi = i;
        else if (s == PM * EE)           idx_edst = i;
    }
    // dict order: features precedes edge_dst and *_ih precedes *_hh.
    // alphabetical order: edge_dst precedes features and *_hh precedes *_ih.
    bool hh_first = (idx_edst >= 0 && idx_feat >= 0 && idx_edst < idx_feat);
    int idx_wih = hh_first ? idx_wB : idx_wA;
    int idx_whh = hh_first ? idx_wA : idx_wB;
    int idx_bih = hh_first ? idx_bB : idx_bA;
    int idx_bhh = hh_first ? idx_bA : idx_bB;

    const float* features = (const float*)d_in[idx_feat];
    const float* w_ih     = (const float*)d_in[idx_wih];   // [P,768,256]
    const float* w_hh     = (const float*)d_in[idx_whh];   // [P,768,256]
    const float* b_ih     = (const float*)d_in[idx_bih];   // [P,768]
    const float* b_hh     = (const float*)d_in[idx_bhh];   // [P,768]
    const float* fc1      = (const float*)d_in[idx_fc1];   // [32,32]
    const float* fc2      = (const float*)d_in[idx_fc2];   // [8,32]
    const int*   emi      = (const int*)d_in[idx_emi];     // [P,E,L]
    const int*   edst     = (const int*)d_in[idx_edst];    // [P,E]
    float* out = (float*)d_out;

    // *** THE FIX ***: device addresses of __device__ scratch. Passing the
    // symbol directly from host code yields the HOST shadow address, which
    // on GB300 (ATS, pageableMemoryAccess=1) is silently dereferenceable by
    // the GPU — the GEMMs were reading/writing host memory while every other
    // kernel used the device copies. cudaGetSymbolAddress is a host-side
    // query: no allocation, graph-capture safe.
    float *p_gi = nullptr, *p_h = nullptr, *p_gh = nullptr;
    cudaGetSymbolAddress((void**)&p_gi, g_gi);
    cudaGetSymbolAddress((void**)&p_h,  g_h);
    cudaGetSymbolAddress((void**)&p_gh, g_gh);

    // zero accumulators
    {
        size_t total = (size_t)PM * NN * DF;
        zero_kernel<<<(unsigned)((total + 255) / 256), 256>>>();
    }

    // normalized node features
    ft_norm_kernel<<<(NN * DD + 255) / 256, 256>>>(features);

    // gi[p] = features @ w_ih[p]^T + b_ih[p]   (per-node precompute: 12x FLOP saving)
    {
        dim3 grid((NN + BM - 1) / BM, G3 / BN, PM);
        sgemm_nt_bias<<<grid, 256>>>(features, 0,
                                     w_ih, b_ih,
                                     p_gi, (size_t)NN * G3, NN);
    }

    size_t gateTotal = (size_t)PM * EE * DF;
    unsigned gateBlocks = (unsigned)((gateTotal + 255) / 256);

    // GRU step 0 (h = 0)
    gru_step0<<<gateBlocks, 256>>>(emi, b_hh);

    // GRU steps 1..3: gh = h @ w_hh^T + b_hh, then gate update
    dim3 ggrid((EE + BM - 1) / BM, G3 / BN, PM);
    for (int l = 1; l < LL; l++) {
        sgemm_nt_bias<<<ggrid, 256>>>(p_h, (size_t)EE * DF,
                                      w_hh, b_hh,
                                      p_gh, (size_t)EE * G3, EE);
        gru_step<<<gateBlocks, 256>>>(emi, l);
    }

    // edge-level attention + segment sum into g_hout
    edge_attn_kernel<<<PM * EE, 256>>>(edst);

    // semantic attention across metapaths
    semantic_kernel<<<(PM * NN * HH) / 256, 256>>>(fc1, fc2);
    beta_kernel<<<1, 32>>>();
    output_kernel<<<(unsigned)(((size_t)NN * DF + 255) / 256), 256>>>(out);
}

// round 13
// speedup vs baseline: 1.7339x; 1.7339x over previous
#include <cuda_runtime.h>
#include <cuda_bf16.h>
#include <math.h>
#include <stdint.h>

// Problem constants
#define NN 20000      // nodes
#define DF 256        // feature dim = H*D
#define PM 3          // metapaths
#define EE 60000      // edges per metapath
#define LL 4          // seq len
#define HH 8          // heads
#define DD 32         // head dim
#define G3 768        // 3 * DF (gate dim)

// ---------------- scratch (device globals; no allocation) ----------------
__device__ float g_ft  [(size_t)NN * DF];            // normalized node features
__device__ float g_gi  [(size_t)PM * NN * G3];       // per-node input gates (+b_ih)
__device__ float g_h   [(size_t)PM * EE * DF];       // GRU hidden per edge (fp32)
__device__ float g_gh  [(size_t)PM * EE * G3];       // hidden gates (+b_hh)
__device__ float g_hout[(size_t)PM * NN * DF];       // per-metapath aggregated output
__device__ float g_s   [PM];
__device__ float g_beta[PM];

// bf16 split-precision operands for tensor-core GEMMs
__device__ __nv_bfloat16 g_fhi [(size_t)NN * DF];
__device__ __nv_bfloat16 g_flo [(size_t)NN * DF];
__device__ __nv_bfloat16 g_wihhi[(size_t)PM * G3 * DF];
__device__ __nv_bfloat16 g_wihlo[(size_t)PM * G3 * DF];
__device__ __nv_bfloat16 g_whhhi[(size_t)PM * G3 * DF];
__device__ __nv_bfloat16 g_whhlo[(size_t)PM * G3 * DF];
__device__ __nv_bfloat16 g_hhi [(size_t)PM * EE * DF];
__device__ __nv_bfloat16 g_hlo [(size_t)PM * EE * DF];

__device__ __forceinline__ float sigmoidf_(float x) {
    return 1.0f / (1.0f + expf(-x));
}

__device__ __forceinline__ uint32_t smem_u32(const void* p) {
    uint32_t a;
    asm("{ .reg .u64 t; cvta.to.shared.u64 t, %1; cvt.u32.u64 %0, t; }" : "=r"(a) : "l"(p));
    return a;
}

// ---- baseline-PTX tensor core ops (sm_80+, no arch-specific features) ----
__device__ __forceinline__ void ldsm4(uint32_t* r, uint32_t addr) {
    asm volatile("ldmatrix.sync.aligned.m8n8.x4.shared.b16 {%0,%1,%2,%3}, [%4];"
                 : "=r"(r[0]), "=r"(r[1]), "=r"(r[2]), "=r"(r[3]) : "r"(addr));
}
__device__ __forceinline__ void ldsm2(uint32_t* r, uint32_t addr) {
    asm volatile("ldmatrix.sync.aligned.m8n8.x2.shared.b16 {%0,%1}, [%2];"
                 : "=r"(r[0]), "=r"(r[1]) : "r"(addr));
}
__device__ __forceinline__ void mma_bf16(float* c, const uint32_t* a, const uint32_t* b) {
    asm volatile(
        "mma.sync.aligned.m16n8k16.row.col.f32.bf16.bf16.f32 "
        "{%0,%1,%2,%3}, {%4,%5,%6,%7}, {%8,%9}, {%0,%1,%2,%3};"
        : "+f"(c[0]), "+f"(c[1]), "+f"(c[2]), "+f"(c[3])
        : "r"(a[0]), "r"(a[1]), "r"(a[2]), "r"(a[3]), "r"(b[0]), "r"(b[1]));
}

// ======== tensor-core GEMM: C[M, 768] = A[M,256] @ W[768,256]^T + bias ========
// split precision: C = Ah*Wh + Ah*Wl + Al*Wh  (each operand bf16, fp32 acc)
// CTA tile 128x64, BK=32, 8 warps (warp tile 32x32 = 2x4 m16n8 tiles).
#define AS 40                    // smem row stride in bf16 (32 + 8 pad; rows 16B aligned)

__global__ __launch_bounds__(256) void tc_gemm(
    const __nv_bfloat16* __restrict__ Ahi, const __nv_bfloat16* __restrict__ Alo,
    size_t aPstride,
    const __nv_bfloat16* __restrict__ Whi, const __nv_bfloat16* __restrict__ Wlo,
    const float* __restrict__ biasBase,
    float* __restrict__ Cbase, size_t cPstride, int M)
{
    __shared__ __align__(16) __nv_bfloat16 As_hi[128 * AS];
    __shared__ __align__(16) __nv_bfloat16 As_lo[128 * AS];
    __shared__ __align__(16) __nv_bfloat16 Bs_hi[64 * AS];
    __shared__ __align__(16) __nv_bfloat16 Bs_lo[64 * AS];

    int tid = threadIdx.x, wid = tid >> 5, lane = tid & 31;
    int p = blockIdx.z, mt = blockIdx.x, nb = blockIdx.y;

    const __nv_bfloat16* Ah = Ahi + (size_t)p * aPstride;
    const __nv_bfloat16* Al = Alo + (size_t)p * aPstride;
    const __nv_bfloat16* Wh = Whi + (size_t)p * G3 * DF;
    const __nv_bfloat16* Wl = Wlo + (size_t)p * G3 * DF;
    const float* bias = biasBase + (size_t)p * G3;
    float* C = Cbase + (size_t)p * cPstride;

    int rows = M - mt * 128; if (rows > 128) rows = 128;

    int wm = (wid >> 1) * 32;      // warp M offset in tile
    int wn = (wid & 1) * 32;       // warp N offset in tile

    float acc[2][4][4];
#pragma unroll
    for (int mi = 0; mi < 2; mi++)
#pragma unroll
        for (int ni = 0; ni < 4; ni++)
#pragma unroll
            for (int r = 0; r < 4; r++) acc[mi][ni][r] = 0.0f;

    uint32_t sAhi = smem_u32(As_hi), sAlo = smem_u32(As_lo);
    uint32_t sBhi = smem_u32(Bs_hi), sBlo = smem_u32(Bs_lo);

    int sub = lane >> 3, lr = lane & 7;
    const uint4 z4 = make_uint4(0u, 0u, 0u, 0u);

    for (int k0 = 0; k0 < DF; k0 += 32) {
        // ---- load A tile 128x32 (hi+lo): 512 16B-chunks, 2 per thread ----
#pragma unroll
        for (int it = 0; it < 2; it++) {
            int chunk = it * 256 + tid;       // 0..511
            int row = chunk >> 2;
            int k8 = (chunk & 3) * 8;
            uint4 vh = z4, vl = z4;
            if (row < rows) {
                size_t g = (size_t)(mt * 128 + row) * DF + k0 + k8;
                vh = *(const uint4*)(Ah + g);
                vl = *(const uint4*)(Al + g);
            }
            *(uint4*)&As_hi[row * AS + k8] = vh;
            *(uint4*)&As_lo[row * AS + k8] = vl;
        }
        // ---- load B tile 64x32 (hi+lo): 256 chunks, 1 per thread ----
        {
            int row = tid >> 2;
            int k8 = (tid & 3) * 8;
            size_t g = (size_t)(nb * 64 + row) * DF + k0 + k8;
            *(uint4*)&Bs_hi[row * AS + k8] = *(const uint4*)(Wh + g);
            *(uint4*)&Bs_lo[row * AS + k8] = *(const uint4*)(Wl + g);
        }
        __syncthreads();

#pragma unroll
        for (int kh = 0; kh < 2; kh++) {      // two k16 halves of BK=32
            int kcA = kh * 16 + (sub >> 1) * 8;          // x4: col by sub/2
            int kcB = kh * 16 + (sub & 1) * 8;           // x2: col by sub&1 (t<16)
            uint32_t ah[2][4], al[2][4];
#pragma unroll
            for (int mi = 0; mi < 2; mi++) {
                uint32_t off = (uint32_t)((wm + mi * 16 + (sub & 1) * 8 + lr) * AS + kcA) * 2u;
                ldsm4(ah[mi], sAhi + off);
                ldsm4(al[mi], sAlo + off);
            }
            uint32_t bh[4][2], bl[4][2];
#pragma unroll
            for (int ni = 0; ni < 4; ni++) {
                uint32_t off = (uint32_t)((wn + ni * 8 + lr) * AS + kcB) * 2u;
                ldsm2(bh[ni], sBhi + off);
                ldsm2(bl[ni], sBlo + off);
            }
#pragma unroll
            for (int mi = 0; mi < 2; mi++)
#pragma unroll
                for (int ni = 0; ni < 4; ni++) {
                    mma_bf16(acc[mi][ni], ah[mi], bh[ni]);
                    mma_bf16(acc[mi][ni], ah[mi], bl[ni]);
                    mma_bf16(acc[mi][ni], al[mi], bh[ni]);
                }
        }
        __syncthreads();
    }

    // ---- epilogue: D[row][col] = acc + bias[col] ----
    int gRow = lane >> 2;            // 0..7
    int pCol = (lane & 3) * 2;       // 0,2,4,6
#pragma unroll
    for (int mi = 0; mi < 2; mi++) {
        int r0 = mt * 128 + wm + mi * 16 + gRow;
#pragma unroll
        for (int ni = 0; ni < 4; ni++) {
            int col = nb * 64 + wn + ni * 8 + pCol;
            float2 b2 = *(const float2*)(bias + col);
            if (r0 < M) {
                float2 o0 = make_float2(acc[mi][ni][0] + b2.x, acc[mi][ni][1] + b2.y);
                *(float2*)(C + (size_t)r0 * G3 + col) = o0;
            }
            if (r0 + 8 < M) {
                float2 o1 = make_float2(acc[mi][ni][2] + b2.x, acc[mi][ni][3] + b2.y);
                *(float2*)(C + (size_t)(r0 + 8) * G3 + col) = o1;
            }
        }
    }
}

// ---------------- fp32 -> bf16 (hi, lo) split ----------------
__global__ void split_kernel(const float* __restrict__ src,
                             __nv_bfloat16* __restrict__ hi,
                             __nv_bfloat16* __restrict__ lo, size_t n) {
    size_t i = (size_t)blockIdx.x * blockDim.x + threadIdx.x;
    if (i >= n) return;
    float x = src[i];
    __nv_bfloat16 h = __float2bfloat16(x);
    hi[i] = h;
    lo[i] = __float2bfloat16(x - __bfloat162float(h));
}

// ---------------- zero scratch that gets accumulated into ----------------
__global__ void zero_kernel() {
    size_t i = (size_t)blockIdx.x * blockDim.x + threadIdx.x;
    size_t total = (size_t)PM * NN * DF;
    if (i < total) g_hout[i] = 0.0f;
    if (i < PM) g_s[i] = 0.0f;
}

// ---------------- ft = l2norm over heads ----------------
__global__ void ft_norm_kernel(const float* __restrict__ feat) {
    int t = blockIdx.x * blockDim.x + threadIdx.x;   // over N*DD
    if (t >= NN * DD) return;
    int n = t / DD, d = t % DD;
    const float* f = feat + (size_t)n * DF + d;
    float v[HH];
    float s = 0.0f;
#pragma unroll
    for (int h = 0; h < HH; h++) { v[h] = f[h * DD]; s += v[h] * v[h]; }
    float inv = 1.0f / fmaxf(sqrtf(s), 1e-12f);
    float* o = g_ft + (size_t)n * DF + d;
#pragma unroll
    for (int h = 0; h < HH; h++) o[h * DD] = v[h] * inv;
}

// ---------------- GRU step 0 (h=0 so gh = b_hh); writes fp32 h + bf16 splits ----------------
__global__ void gru_step0(const int* __restrict__ emi, const float* __restrict__ b_hh) {
    size_t i = (size_t)blockIdx.x * blockDim.x + threadIdx.x;
    size_t total = (size_t)PM * EE * DF;
    if (i >= total) return;
    int k = (int)(i & 255);
    size_t pe = i >> 8;                    // p*EE + e
    int p = (int)(pe / EE);
    int node = emi[pe * LL + 0];
    const float* gi = g_gi + ((size_t)p * NN + node) * G3;
    const float* bh = b_hh + (size_t)p * G3;
    float r  = sigmoidf_(gi[k]       + bh[k]);
    float z  = sigmoidf_(gi[k + 256] + bh[k + 256]);
    float nv = tanhf(gi[k + 512] + r * bh[k + 512]);
    float hn = (1.0f - z) * nv;
    g_h[i] = hn;
    __nv_bfloat16 hb = __float2bfloat16(hn);
    g_hhi[i] = hb;
    g_hlo[i] = __float2bfloat16(hn - __bfloat162float(hb));
}

// ---------------- GRU step l (1..3); g_gh contains +b_hh ----------------
__global__ void gru_step(const int* __restrict__ emi, int l) {
    size_t i = (size_t)blockIdx.x * blockDim.x + threadIdx.x;
    size_t total = (size_t)PM * EE * DF;
    if (i >= total) return;
    int k = (int)(i & 255);
    size_t pe = i >> 8;
    int p = (int)(pe / EE);
    int node = emi[pe * LL + l];
    const float* gi = g_gi + ((size_t)p * NN + node) * G3;
    const float* gh = g_gh + pe * G3;
    float r  = sigmoidf_(gi[k]       + gh[k]);
    float z  = sigmoidf_(gi[k + 256] + gh[k + 256]);
    float nv = tanhf(gi[k + 512] + r * gh[k + 512]);
    float hp = g_h[i];
    float hn = (1.0f - z) * nv + z * hp;
    g_h[i] = hn;
    if (l < LL - 1) {
        __nv_bfloat16 hb = __float2bfloat16(hn);
        g_hhi[i] = hb;
        g_hlo[i] = __float2bfloat16(hn - __bfloat162float(hb));
    }
}

// ---------------- edge attention + segment sum ----------------
__global__ __launch_bounds__(256) void edge_attn_kernel(const int* __restrict__ edst) {
    int pe = blockIdx.x;                   // p*EE + e
    int p = pe / EE;
    int k = threadIdx.x;
    int h = k >> 5, d = k & 31;

    float v = g_h[(size_t)pe * DF + k];

    __shared__ float sv[DF];
    __shared__ float snorm[DD];
    __shared__ float ssim[HH];

    sv[k] = v * v;
    __syncthreads();
    if (k < DD) {
        float s = 0.0f;
#pragma unroll
        for (int hh = 0; hh < HH; hh++) s += sv[hh * DD + k];
        snorm[k] = fmaxf(sqrtf(s), 1e-12f);
    }
    __syncthreads();

    float eft = v / snorm[d];

    int dst = edst[pe];
    float ftv = g_ft[(size_t)dst * DF + k];
    float prod = eft * ftv;
#pragma unroll
    for (int off = 16; off > 0; off >>= 1)
        prod += __shfl_down_sync(0xFFFFFFFFu, prod, off);
    if ((k & 31) == 0) ssim[h] = prod;
    __syncthreads();

    float mx = ssim[0];
#pragma unroll
    for (int i = 1; i < HH; i++) mx = fmaxf(mx, ssim[i]);
    float den = 0.0f;
#pragma unroll
    for (int i = 0; i < HH; i++) den += expf(ssim[i] - mx);
    float a = expf(ssim[h] - mx) / den;

    atomicAdd(&g_hout[((size_t)p * NN + dst) * DF + k], eft * a);
}

// ---------------- semantic attention scores ----------------
__global__ __launch_bounds__(256) void semantic_kernel(const float* __restrict__ fc1,
                                                       const float* __restrict__ fc2) {
    __shared__ float s1[DD * DD];
    __shared__ float s2[HH * DD];
    __shared__ float red[256];
    int tid = threadIdx.x;
    for (int i = tid; i < DD * DD; i += 256) s1[i] = fc1[i];
    if (tid < HH * DD) s2[tid] = fc2[tid];
    __syncthreads();

    int g = blockIdx.x * 256 + tid;   // over PM*NN*HH
    int h = g % HH;
    int pn = g / HH;
    const float* hvp = g_hout + (size_t)pn * DF + h * DD;
    float hv[DD];
#pragma unroll
    for (int i = 0; i < 8; i++) {
        float4 v4 = *(const float4*)(hvp + i * 4);
        hv[i * 4 + 0] = v4.x; hv[i * 4 + 1] = v4.y;
        hv[i * 4 + 2] = v4.z; hv[i * 4 + 3] = v4.w;
    }
    float acc = 0.0f;
    for (int e = 0; e < DD; e++) {
        float s = 0.0f;
#pragma unroll
        for (int d = 0; d < DD; d++) s += hv[d] * s1[e * DD + d];
        acc += tanhf(s) * s2[h * DD + e];
    }

    red[tid] = acc;
    __syncthreads();
    for (int s = 128; s > 0; s >>= 1) {
        if (tid < s) red[tid] += red[tid + s];
        __syncthreads();
    }
    if (tid == 0) {
        int p = (blockIdx.x * 256) / (NN * HH);
        atomicAdd(&g_s[p], red[0]);
    }
}

__global__ void beta_kernel() {
    if (threadIdx.x == 0 && blockIdx.x == 0) {
        float s[PM];
        float mx = -1e30f;
#pragma unroll
        for (int p = 0; p < PM; p++) { s[p] = g_s[p] / (float)NN; mx = fmaxf(mx, s[p]); }
        float den = 0.0f;
#pragma unroll
        for (int p = 0; p < PM; p++) { s[p] = expf(s[p] - mx); den += s[p]; }
#pragma unroll
        for (int p = 0; p < PM; p++) g_beta[p] = s[p] / den;
    }
}

__global__ void output_kernel(float* __restrict__ out) {
    size_t i = (size_t)blockIdx.x * blockDim.x + threadIdx.x;
    const size_t total = (size_t)NN * DF;
    if (i >= total) return;
    out[i] = g_beta[0] * g_hout[i]
           + g_beta[1] * g_hout[total + i]
           + g_beta[2] * g_hout[2 * total + i];
}

// ---------------- launch ----------------
extern "C" void kernel_launch(void* const* d_in, const int* in_sizes, int n_in,
                              void* d_out, int out_size) {
    // bind inputs by SIZE
    int idx_feat = -1, idx_fc1 = -1, idx_fc2 = -1, idx_emi = -1, idx_edst = -1;
    int idx_wA = -1, idx_wB = -1, idx_bA = -1, idx_bB = -1;
    for (int i = 0; i < n_in; i++) {
        int s = in_sizes[i];
        if      (s == NN * DF)           idx_feat = i;
        else if (s == PM * G3 * DF)      { if (idx_wA < 0) idx_wA = i; else idx_wB = i; }
        else if (s == PM * G3)           { if (idx_bA < 0) idx_bA = i; else idx_bB = i; }
        else if (s == DD * DD)           idx_fc1 = i;
        else if (s == HH * DD)           idx_fc2 = i;
        else if (s == PM * EE * LL)      idx_emi = i;
        else if (s == PM * EE)           idx_edst = i;
    }
    bool hh_first = (idx_edst >= 0 && idx_feat >= 0 && idx_edst < idx_feat);
    int idx_wih = hh_first ? idx_wB : idx_wA;
    int idx_whh = hh_first ? idx_wA : idx_wB;
    int idx_bih = hh_first ? idx_bB : idx_bA;
    int idx_bhh = hh_first ? idx_bA : idx_bB;

    const float* features = (const float*)d_in[idx_feat];
    const float* w_ih     = (const float*)d_in[idx_wih];
    const float* w_hh     = (const float*)d_in[idx_whh];
    const float* b_ih     = (const float*)d_in[idx_bih];
    const float* b_hh     = (const float*)d_in[idx_bhh];
    const float* fc1      = (const float*)d_in[idx_fc1];
    const float* fc2      = (const float*)d_in[idx_fc2];
    const int*   emi      = (const int*)d_in[idx_emi];
    const int*   edst     = (const int*)d_in[idx_edst];
    float* out = (float*)d_out;

    // device addresses of __device__ scratch (NOT host shadow symbols!)
    float *p_gi, *p_gh;
    __nv_bfloat16 *p_fhi, *p_flo, *p_wihhi, *p_wihlo, *p_whhhi, *p_whhlo, *p_hhi, *p_hlo;
    cudaGetSymbolAddress((void**)&p_gi,    g_gi);
    cudaGetSymbolAddress((void**)&p_gh,    g_gh);
    cudaGetSymbolAddress((void**)&p_fhi,   g_fhi);
    cudaGetSymbolAddress((void**)&p_flo,   g_flo);
    cudaGetSymbolAddress((void**)&p_wihhi, g_wihhi);
    cudaGetSymbolAddress((void**)&p_wihlo, g_wihlo);
    cudaGetSymbolAddress((void**)&p_whhhi, g_whhhi);
    cudaGetSymbolAddress((void**)&p_whhlo, g_whhlo);
    cudaGetSymbolAddress((void**)&p_hhi,   g_hhi);
    cudaGetSymbolAddress((void**)&p_hlo,   g_hlo);

    // zero accumulators
    {
        size_t total = (size_t)PM * NN * DF;
        zero_kernel<<<(unsigned)((total + 255) / 256), 256>>>();
    }

    ft_norm_kernel<<<(NN * DD + 255) / 256, 256>>>(features);

    // split conversions (once per launch)
    {
        size_t nf = (size_t)NN * DF;
        split_kernel<<<(unsigned)((nf + 255) / 256), 256>>>(features, p_fhi, p_flo, nf);
        size_t nw = (size_t)PM * G3 * DF;
        split_kernel<<<(unsigned)((nw + 255) / 256), 256>>>(w_ih, p_wihhi, p_wihlo, nw);
        split_kernel<<<(unsigned)((nw + 255) / 256), 256>>>(w_hh, p_whhhi, p_whhlo, nw);
    }

    // gi[p] = features @ w_ih[p]^T + b_ih[p]  (tensor cores, split precision)
    {
        dim3 grid((NN + 127) / 128, 12, PM);
        tc_gemm<<<grid, 256>>>(p_fhi, p_flo, 0,
                               p_wihhi, p_wihlo, b_ih,
                               p_gi, (size_t)NN * G3, NN);
    }

    size_t gateTotal = (size_t)PM * EE * DF;
    unsigned gateBlocks = (unsigned)((gateTotal + 255) / 256);

    gru_step0<<<gateBlocks, 256>>>(emi, b_hh);

    dim3 ggrid((EE + 127) / 128, 12, PM);
    for (int l = 1; l < LL; l++) {
        tc_gemm<<<ggrid, 256>>>(p_hhi, p_hlo, (size_t)EE * DF,
                                p_whhhi, p_whhlo, b_hh,
                                p_gh, (size_t)EE * G3, EE);
        gru_step<<<gateBlocks, 256>>>(emi, l);
    }

    edge_attn_kernel<<<PM * EE, 256>>>(edst);

    semantic_kernel<<<(PM * NN * HH) / 256, 256>>>(fc1, fc2);
    beta_kernel<<<1, 32>>>();
    output_kernel<<<(unsigned)(((size_t)NN * DF + 255) / 256), 256>>>(out);
}

// round 14
// speedup vs baseline: 2.3070x; 1.3305x over previous
#include <cuda_runtime.h>
#include <cuda_bf16.h>
#include <math.h>
#include <stdint.h>

// Problem constants
#define NN 20000      // nodes
#define DF 256        // feature dim = H*D
#define PM 3          // metapaths
#define EE 60000      // edges per metapath
#define LL 4          // seq len
#define HH 8          // heads
#define DD 32         // head dim
#define G3 768        // 3 * DF (gate dim)

// ---------------- scratch (device globals; no allocation) ----------------
__device__ float g_ft  [(size_t)NN * DF];
__device__ float g_gi  [(size_t)PM * NN * G3];
__device__ float g_h   [(size_t)PM * EE * DF];
__device__ float g_gh  [(size_t)PM * EE * G3];
__device__ float g_hout[(size_t)PM * NN * DF];
__device__ float g_s   [PM];
__device__ float g_beta[PM];

__device__ __nv_bfloat16 g_fhi [(size_t)NN * DF];
__device__ __nv_bfloat16 g_flo [(size_t)NN * DF];
__device__ __nv_bfloat16 g_wihhi[(size_t)PM * G3 * DF];
__device__ __nv_bfloat16 g_wihlo[(size_t)PM * G3 * DF];
__device__ __nv_bfloat16 g_whhhi[(size_t)PM * G3 * DF];
__device__ __nv_bfloat16 g_whhlo[(size_t)PM * G3 * DF];
__device__ __nv_bfloat16 g_hhi [(size_t)PM * EE * DF];
__device__ __nv_bfloat16 g_hlo [(size_t)PM * EE * DF];

// fast transcendentals (rel err ~2^-21; fine vs 1e-3 threshold)
__device__ __forceinline__ float fsig(float x) {
    return __fdividef(1.0f, 1.0f + __expf(-x));
}
__device__ __forceinline__ float ftanh_(float x) {
    return 1.0f - __fdividef(2.0f, __expf(2.0f * x) + 1.0f);
}

__device__ __forceinline__ uint32_t smem_u32(const void* p) {
    uint32_t a;
    asm("{ .reg .u64 t; cvta.to.shared.u64 t, %1; cvt.u32.u64 %0, t; }" : "=r"(a) : "l"(p));
    return a;
}

// ---- baseline-PTX tensor core + async copy (sm_80 features only) ----
__device__ __forceinline__ void ldsm4(uint32_t* r, uint32_t addr) {
    asm volatile("ldmatrix.sync.aligned.m8n8.x4.shared.b16 {%0,%1,%2,%3}, [%4];"
                 : "=r"(r[0]), "=r"(r[1]), "=r"(r[2]), "=r"(r[3]) : "r"(addr));
}
__device__ __forceinline__ void mma_bf16(float* c, const uint32_t* a, const uint32_t* b) {
    asm volatile(
        "mma.sync.aligned.m16n8k16.row.col.f32.bf16.bf16.f32 "
        "{%0,%1,%2,%3}, {%4,%5,%6,%7}, {%8,%9}, {%0,%1,%2,%3};"
        : "+f"(c[0]), "+f"(c[1]), "+f"(c[2]), "+f"(c[3])
        : "r"(a[0]), "r"(a[1]), "r"(a[2]), "r"(a[3]), "r"(b[0]), "r"(b[1]));
}
__device__ __forceinline__ void cpa16(uint32_t saddr, const void* g) {
    asm volatile("cp.async.cg.shared.global [%0], [%1], 16;" :: "r"(saddr), "l"(g));
}
#define CP_COMMIT()  asm volatile("cp.async.commit_group;" ::: "memory")
#define CP_WAIT(n)   asm volatile("cp.async.wait_group %0;" :: "n"(n) : "memory")

// ======== tensor-core GEMM: C[M,768] = A[M,256] @ W[768,256]^T + bias ========
// split precision: C = Ah*Wh + Ah*Wl + Al*Wh. CTA tile 128x128, BK=32,
// 2-stage cp.async pipeline. 8 warps, warp tile 32x64.
#define AS 40                          // smem row stride in bf16 (conflict-free for ldmatrix)
#define STG 10240                      // one stage of one operand: 128*40*2 bytes
// dynamic smem regions: AHI[2], ALO[2], BHI[2], BLO[2]
#define OFF_AHI 0
#define OFF_ALO 20480
#define OFF_BHI 40960
#define OFF_BLO 61440
#define GEMM_SMEM 81920

__global__ __launch_bounds__(256, 2) void tc_gemm(
    const __nv_bfloat16* __restrict__ Ahi, const __nv_bfloat16* __restrict__ Alo,
    size_t aPstride,
    const __nv_bfloat16* __restrict__ Whi, const __nv_bfloat16* __restrict__ Wlo,
    const float* __restrict__ biasBase,
    float* __restrict__ Cbase, size_t cPstride, int M)
{
    extern __shared__ __align__(16) char sm[];
    uint32_t sb = smem_u32(sm);

    int tid = threadIdx.x, wid = tid >> 5, lane = tid & 31;
    int p = blockIdx.z, mt = blockIdx.x, nb = blockIdx.y;

    const __nv_bfloat16* Ah = Ahi + (size_t)p * aPstride;
    const __nv_bfloat16* Al = Alo + (size_t)p * aPstride;
    const __nv_bfloat16* Wh = Whi + (size_t)p * G3 * DF;
    const __nv_bfloat16* Wl = Wlo + (size_t)p * G3 * DF;
    const float* bias = biasBase + (size_t)p * G3;
    float* C = Cbase + (size_t)p * cPstride;

    int Mm1 = M - 1;
    int wm = (wid >> 1) * 32;          // warp M offset: 0,32,64,96
    int wn = (wid & 1) * 64;           // warp N offset: 0,64

    float acc[2][8][4];
#pragma unroll
    for (int mi = 0; mi < 2; mi++)
#pragma unroll
        for (int ni = 0; ni < 8; ni++)
#pragma unroll
            for (int r = 0; r < 4; r++) acc[mi][ni][r] = 0.0f;

    // per-thread load coords (16B chunks): 2 chunks per operand per stage
    int ldrow0 = tid >> 2;                       // rows 0..63  (it=0)
    int ldk8   = (tid & 3) * 8;
    // A global rows (clamped; invalid rows masked at epilogue)
    int arow0 = mt * 128 + ldrow0;      if (arow0 > Mm1) arow0 = Mm1;
    int arow1 = mt * 128 + ldrow0 + 64; if (arow1 > Mm1) arow1 = Mm1;
    int brow0 = nb * 128 + ldrow0;
    int brow1 = nb * 128 + ldrow0 + 64;
    uint32_t so0 = (uint32_t)(ldrow0 * AS + ldk8) * 2u;
    uint32_t so1 = (uint32_t)((ldrow0 + 64) * AS + ldk8) * 2u;

#define LOAD_STAGE(stg, k0) do {                                              \
    uint32_t _s = (uint32_t)(stg) * STG;                                      \
    size_t _k = (size_t)(k0) + ldk8;                                          \
    cpa16(sb + OFF_AHI + _s + so0, Ah + (size_t)arow0 * DF + _k);             \
    cpa16(sb + OFF_AHI + _s + so1, Ah + (size_t)arow1 * DF + _k);             \
    cpa16(sb + OFF_ALO + _s + so0, Al + (size_t)arow0 * DF + _k);             \
    cpa16(sb + OFF_ALO + _s + so1, Al + (size_t)arow1 * DF + _k);             \
    cpa16(sb + OFF_BHI + _s + so0, Wh + (size_t)brow0 * DF + _k);             \
    cpa16(sb + OFF_BHI + _s + so1, Wh + (size_t)brow1 * DF + _k);             \
    cpa16(sb + OFF_BLO + _s + so0, Wl + (size_t)brow0 * DF + _k);             \
    cpa16(sb + OFF_BLO + _s + so1, Wl + (size_t)brow1 * DF + _k);             \
    CP_COMMIT();                                                              \
} while (0)

    int sub = lane >> 3, lr = lane & 7;

    LOAD_STAGE(0, 0);

    for (int ks = 0; ks < 8; ks++) {           // 8 K-stages of 32
        if (ks < 7) {
            LOAD_STAGE((ks + 1) & 1, (ks + 1) * 32);
            CP_WAIT(1);
        } else {
            CP_WAIT(0);
        }
        __syncthreads();

        uint32_t st = (uint32_t)(ks & 1) * STG;
        uint32_t aHi = sb + OFF_AHI + st, aLo = sb + OFF_ALO + st;
        uint32_t bHi = sb + OFF_BHI + st, bLo = sb + OFF_BLO + st;

#pragma unroll
        for (int kh = 0; kh < 2; kh++) {
            // A fragments (m16k16 x2 tiles), hi+lo
            uint32_t ah[2][4], al[2][4];
            int kcA = kh * 16 + (sub >> 1) * 8;
#pragma unroll
            for (int mi = 0; mi < 2; mi++) {
                uint32_t off = (uint32_t)((wm + mi * 16 + (sub & 1) * 8 + lr) * AS + kcA) * 2u;
                ldsm4(ah[mi], aHi + off);
                ldsm4(al[mi], aLo + off);
            }
            // B: pairs of n8 tiles via x4 (q=sub: mat = (pair-half, k-half))
            int brow_f = wn + (sub >> 1) * 8 + lr;
            int bcol_f = kh * 16 + (sub & 1) * 8;
#pragma unroll
            for (int nip = 0; nip < 4; nip++) {
                uint32_t off = (uint32_t)((brow_f + nip * 16) * AS + bcol_f) * 2u;
                uint32_t bh[4], bl[4];
                ldsm4(bh, bHi + off);
                ldsm4(bl, bLo + off);
#pragma unroll
                for (int mi = 0; mi < 2; mi++) {
                    mma_bf16(acc[mi][nip * 2 + 0], ah[mi], bh + 0);
                    mma_bf16(acc[mi][nip * 2 + 0], ah[mi], bl + 0);
                    mma_bf16(acc[mi][nip * 2 + 0], al[mi], bh + 0);
                    mma_bf16(acc[mi][nip * 2 + 1], ah[mi], bh + 2);
                    mma_bf16(acc[mi][nip * 2 + 1], ah[mi], bl + 2);
                    mma_bf16(acc[mi][nip * 2 + 1], al[mi], bh + 2);
                }
            }
        }
        __syncthreads();
    }

    // ---- epilogue: D = acc + bias ----
    int gRow = lane >> 2;
    int pCol = (lane & 3) * 2;
#pragma unroll
    for (int mi = 0; mi < 2; mi++) {
        int r0 = mt * 128 + wm + mi * 16 + gRow;
#pragma unroll
        for (int ni = 0; ni < 8; ni++) {
            int col = nb * 128 + wn + ni * 8 + pCol;
            float2 b2 = *(const float2*)(bias + col);
            if (r0 < M) {
                float2 o0 = make_float2(acc[mi][ni][0] + b2.x, acc[mi][ni][1] + b2.y);
                *(float2*)(C + (size_t)r0 * G3 + col) = o0;
            }
            if (r0 + 8 < M) {
                float2 o1 = make_float2(acc[mi][ni][2] + b2.x, acc[mi][ni][3] + b2.y);
                *(float2*)(C + (size_t)(r0 + 8) * G3 + col) = o1;
            }
        }
    }
}

// ---------------- fp32 -> bf16 (hi, lo) split ----------------
__global__ void split_kernel(const float* __restrict__ src,
                             __nv_bfloat16* __restrict__ hi,
                             __nv_bfloat16* __restrict__ lo, size_t n) {
    size_t i = (size_t)blockIdx.x * blockDim.x + threadIdx.x;
    if (i >= n) return;
    float x = src[i];
    __nv_bfloat16 h = __float2bfloat16(x);
    hi[i] = h;
    lo[i] = __float2bfloat16(x - __bfloat162float(h));
}

__global__ void zero_kernel() {
    size_t i = (size_t)blockIdx.x * blockDim.x + threadIdx.x;
    size_t total = (size_t)PM * NN * DF;
    if (i < total) g_hout[i] = 0.0f;
    if (i < PM) g_s[i] = 0.0f;
}

// ---------------- ft = l2norm over heads ----------------
__global__ void ft_norm_kernel(const float* __restrict__ feat) {
    int t = blockIdx.x * blockDim.x + threadIdx.x;
    if (t >= NN * DD) return;
    int n = t / DD, d = t % DD;
    const float* f = feat + (size_t)n * DF + d;
    float v[HH];
    float s = 0.0f;
#pragma unroll
    for (int h = 0; h < HH; h++) { v[h] = f[h * DD]; s += v[h] * v[h]; }
    float inv = __fdividef(1.0f, fmaxf(sqrtf(s), 1e-12f));
    float* o = g_ft + (size_t)n * DF + d;
#pragma unroll
    for (int h = 0; h < HH; h++) o[h * DD] = v[h] * inv;
}

// ---------------- GRU step 0 (h=0 so gh = b_hh) ----------------
__global__ void gru_step0(const int* __restrict__ emi, const float* __restrict__ b_hh) {
    size_t i = (size_t)blockIdx.x * blockDim.x + threadIdx.x;
    size_t total = (size_t)PM * EE * DF;
    if (i >= total) return;
    int k = (int)(i & 255);
    size_t pe = i >> 8;
    int p = (int)(pe / EE);
    int node = emi[pe * LL + 0];
    const float* gi = g_gi + ((size_t)p * NN + node) * G3;
    const float* bh = b_hh + (size_t)p * G3;
    float r  = fsig(gi[k]       + bh[k]);
    float z  = fsig(gi[k + 256] + bh[k + 256]);
    float nv = ftanh_(gi[k + 512] + r * bh[k + 512]);
    float hn = (1.0f - z) * nv;
    g_h[i] = hn;
    __nv_bfloat16 hb = __float2bfloat16(hn);
    g_hhi[i] = hb;
    g_hlo[i] = __float2bfloat16(hn - __bfloat162float(hb));
}

// ---------------- GRU step l (1..3) ----------------
__global__ void gru_step(const int* __restrict__ emi, int l) {
    size_t i = (size_t)blockIdx.x * blockDim.x + threadIdx.x;
    size_t total = (size_t)PM * EE * DF;
    if (i >= total) return;
    int k = (int)(i & 255);
    size_t pe = i >> 8;
    int p = (int)(pe / EE);
    int node = emi[pe * LL + l];
    const float* gi = g_gi + ((size_t)p * NN + node) * G3;
    const float* gh = g_gh + pe * G3;
    float r  = fsig(gi[k]       + gh[k]);
    float z  = fsig(gi[k + 256] + gh[k + 256]);
    float nv = ftanh_(gi[k + 512] + r * gh[k + 512]);
    float hp = g_h[i];
    float hn = (1.0f - z) * nv + z * hp;
    g_h[i] = hn;
    if (l < LL - 1) {
        __nv_bfloat16 hb = __float2bfloat16(hn);
        g_hhi[i] = hb;
        g_hlo[i] = __float2bfloat16(hn - __bfloat162float(hb));
    }
}

// ---------------- edge attention + segment sum (MUFU-minimized) ----------------
__global__ __launch_bounds__(256) void edge_attn_kernel(const int* __restrict__ edst) {
    int pe = blockIdx.x;
    int p = pe / EE;
    int k = threadIdx.x;
    int h = k >> 5, d = k & 31;

    float v = g_h[(size_t)pe * DF + k];

    __shared__ float sv[DF];
    __shared__ float sinvn[DD];     // 1/norm per d
    __shared__ float ssim[HH];
    __shared__ float sexp[HH];
    __shared__ float sinvden;

    sv[k] = v * v;
    __syncthreads();
    if (k < DD) {
        float s = 0.0f;
#pragma unroll
        for (int hh = 0; hh < HH; hh++) s += sv[hh * DD + k];
        sinvn[k] = __fdividef(1.0f, fmaxf(sqrtf(s), 1e-12f));
    }
    __syncthreads();

    float eft = v * sinvn[d];

    int dst = edst[pe];
    float ftv = g_ft[(size_t)dst * DF + k];
    float prod = eft * ftv;
#pragma unroll
    for (int off = 16; off > 0; off >>= 1)
        prod += __shfl_down_sync(0xFFFFFFFFu, prod, off);
    if ((k & 31) == 0) ssim[h] = prod;
    __syncthreads();

    // softmax over 8 heads: 8 threads do exp, 1 does the reciprocal
    if (k < HH) {
        float mx = ssim[0];
#pragma unroll
        for (int i = 1; i < HH; i++) mx = fmaxf(mx, ssim[i]);
        sexp[k] = __expf(ssim[k] - mx);
    }
    __syncthreads();
    if (k == 0) {
        float den = 0.0f;
#pragma unroll
        for (int i = 0; i < HH; i++) den += sexp[i];
        sinvden = __fdividef(1.0f, den);
    }
    __syncthreads();

    float a = sexp[h] * sinvden;
    atomicAdd(&g_hout[((size_t)p * NN + dst) * DF + k], eft * a);
}

// ---------------- semantic attention scores ----------------
__global__ __launch_bounds__(256) void semantic_kernel(const float* __restrict__ fc1,
                                                       const float* __restrict__ fc2) {
    __shared__ float s1[DD * DD];
    __shared__ float s2[HH * DD];
    __shared__ float red[256];
    int tid = threadIdx.x;
    for (int i = tid; i < DD * DD; i += 256) s1[i] = fc1[i];
    if (tid < HH * DD) s2[tid] = fc2[tid];
    __syncthreads();

    int g = blockIdx.x * 256 + tid;
    int h = g % HH;
    int pn = g / HH;
    const float* hvp = g_hout + (size_t)pn * DF + h * DD;
    float hv[DD];
#pragma unroll
    for (int i = 0; i < 8; i++) {
        float4 v4 = *(const float4*)(hvp + i * 4);
        hv[i * 4 + 0] = v4.x; hv[i * 4 + 1] = v4.y;
        hv[i * 4 + 2] = v4.z; hv[i * 4 + 3] = v4.w;
    }
    float acc = 0.0f;
    for (int e = 0; e < DD; e++) {
        float s = 0.0f;
#pragma unroll
        for (int d = 0; d < DD; d++) s += hv[d] * s1[e * DD + d];
        acc += ftanh_(s) * s2[h * DD + e];
    }

    red[tid] = acc;
    __syncthreads();
    for (int s = 128; s > 0; s >>= 1) {
        if (tid < s) red[tid] += red[tid + s];
        __syncthreads();
    }
    if (tid == 0) {
        int p = (blockIdx.x * 256) / (NN * HH);
        atomicAdd(&g_s[p], red[0]);
    }
}

__global__ void beta_kernel() {
    if (threadIdx.x == 0 && blockIdx.x == 0) {
        float s[PM];
        float mx = -1e30f;
#pragma unroll
        for (int p = 0; p < PM; p++) { s[p] = g_s[p] / (float)NN; mx = fmaxf(mx, s[p]); }
        float den = 0.0f;
#pragma unroll
        for (int p = 0; p < PM; p++) { s[p] = expf(s[p] - mx); den += s[p]; }
#pragma unroll
        for (int p = 0; p < PM; p++) g_beta[p] = s[p] / den;
    }
}

__global__ void output_kernel(float* __restrict__ out) {
    size_t i = (size_t)blockIdx.x * blockDim.x + threadIdx.x;
    const size_t total = (size_t)NN * DF;
    if (i >= total) return;
    out[i] = g_beta[0] * g_hout[i]
           + g_beta[1] * g_hout[total + i]
           + g_beta[2] * g_hout[2 * total + i];
}

// ---------------- launch ----------------
extern "C" void kernel_launch(void* const* d_in, const int* in_sizes, int n_in,
                              void* d_out, int out_size) {
    // bind inputs by SIZE
    int idx_feat = -1, idx_fc1 = -1, idx_fc2 = -1, idx_emi = -1, idx_edst = -1;
    int idx_wA = -1, idx_wB = -1, idx_bA = -1, idx_bB = -1;
    for (int i = 0; i < n_in; i++) {
        int s = in_sizes[i];
        if      (s == NN * DF)           idx_feat = i;
        else if (s == PM * G3 * DF)      { if (idx_wA < 0) idx_wA = i; else idx_wB = i; }
        else if (s == PM * G3)           { if (idx_bA < 0) idx_bA = i; else idx_bB = i; }
        else if (s == DD * DD)           idx_fc1 = i;
        else if (s == HH * DD)           idx_fc2 = i;
        else if (s == PM * EE * LL)      idx_emi = i;
        else if (s == PM * EE)           idx_edst = i;
    }
    bool hh_first = (idx_edst >= 0 && idx_feat >= 0 && idx_edst < idx_feat);
    int idx_wih = hh_first ? idx_wB : idx_wA;
    int idx_whh = hh_first ? idx_wA : idx_wB;
    int idx_bih = hh_first ? idx_bB : idx_bA;
    int idx_bhh = hh_first ? idx_bA : idx_bB;

    const float* features = (const float*)d_in[idx_feat];
    const float* w_ih     = (const float*)d_in[idx_wih];
    const float* w_hh     = (const float*)d_in[idx_whh];
    const float* b_ih     = (const float*)d_in[idx_bih];
    const float* b_hh     = (const float*)d_in[idx_bhh];
    const float* fc1      = (const float*)d_in[idx_fc1];
    const float* fc2      = (const float*)d_in[idx_fc2];
    const int*   emi      = (const int*)d_in[idx_emi];
    const int*   edst     = (const int*)d_in[idx_edst];
    float* out = (float*)d_out;

    // device addresses of __device__ scratch (NOT host shadow symbols!)
    float *p_gi, *p_gh;
    __nv_bfloat16 *p_fhi, *p_flo, *p_wihhi, *p_wihlo, *p_whhhi, *p_whhlo, *p_hhi, *p_hlo;
    cudaGetSymbolAddress((void**)&p_gi,    g_gi);
    cudaGetSymbolAddress((void**)&p_gh,    g_gh);
    cudaGetSymbolAddress((void**)&p_fhi,   g_fhi);
    cudaGetSymbolAddress((void**)&p_flo,   g_flo);
    cudaGetSymbolAddress((void**)&p_wihhi, g_wihhi);
    cudaGetSymbolAddress((void**)&p_wihlo, g_wihlo);
    cudaGetSymbolAddress((void**)&p_whhhi, g_whhhi);
    cudaGetSymbolAddress((void**)&p_whhlo, g_whhlo);
    cudaGetSymbolAddress((void**)&p_hhi,   g_hhi);
    cudaGetSymbolAddress((void**)&p_hlo,   g_hlo);

    cudaFuncSetAttribute(tc_gemm, cudaFuncAttributeMaxDynamicSharedMemorySize, GEMM_SMEM);

    {
        size_t total = (size_t)PM * NN * DF;
        zero_kernel<<<(unsigned)((total + 255) / 256), 256>>>();
    }

    ft_norm_kernel<<<(NN * DD + 255) / 256, 256>>>(features);

    {
        size_t nf = (size_t)NN * DF;
        split_kernel<<<(unsigned)((nf + 255) / 256), 256>>>(features, p_fhi, p_flo, nf);
        size_t nw = (size_t)PM * G3 * DF;
        split_kernel<<<(unsigned)((nw + 255) / 256), 256>>>(w_ih, p_wihhi, p_wihlo, nw);
        split_kernel<<<(unsigned)((nw + 255) / 256), 256>>>(w_hh, p_whhhi, p_whhlo, nw);
    }

    // gi[p] = features @ w_ih[p]^T + b_ih[p]
    {
        dim3 grid((NN + 127) / 128, 6, PM);
        tc_gemm<<<grid, 256, GEMM_SMEM>>>(p_fhi, p_flo, 0,
                                          p_wihhi, p_wihlo, b_ih,
                                          p_gi, (size_t)NN * G3, NN);
    }

    size_t gateTotal = (size_t)PM * EE * DF;
    unsigned gateBlocks = (unsigned)((gateTotal + 255) / 256);

    gru_step0<<<gateBlocks, 256>>>(emi, b_hh);

    dim3 ggrid((EE + 127) / 128, 6, PM);
    for (int l = 1; l < LL; l++) {
        tc_gemm<<<ggrid, 256, GEMM_SMEM>>>(p_hhi, p_hlo, (size_t)EE * DF,
                                           p_whhhi, p_whhlo, b_hh,
                                           p_gh, (size_t)EE * G3, EE);
        gru_step<<<gateBlocks, 256>>>(emi, l);
    }

    edge_attn_kernel<<<PM * EE, 256>>>(edst);

    semantic_kernel<<<(PM * NN * HH) / 256, 256>>>(fc1, fc2);
    beta_kernel<<<1, 32>>>();
    output_kernel<<<(unsigned)(((size_t)NN * DF + 255) / 256), 256>>>(out);
}

// round 16
// speedup vs baseline: 2.6640x; 1.1548x over previous
#include <cuda_runtime.h>
#include <cuda_bf16.h>
#include <math.h>
#include <stdint.h>

// Problem constants
#define NN 20000      // nodes
#define DF 256        // feature dim = H*D
#define PM 3          // metapaths
#define EE 60000      // edges per metapath
#define LL 4          // seq len
#define HH 8          // heads
#define DD 32         // head dim
#define G3 768        // 3 * DF (gate dim)

// ---------------- scratch (device globals; no allocation) ----------------
__device__ float g_ft  [(size_t)NN * DF];
__device__ float g_gi  [(size_t)PM * NN * G3];
// ping-pong hidden state (avoids same-launch read/write race in fused GRU)
__device__ float g_h0  [(size_t)PM * EE * DF];
__device__ float g_h1  [(size_t)PM * EE * DF];
__device__ float g_hout[(size_t)PM * NN * DF];
__device__ float g_s   [PM];
__device__ float g_beta[PM];

__device__ __nv_bfloat16 g_fhi [(size_t)NN * DF];
__device__ __nv_bfloat16 g_flo [(size_t)NN * DF];
__device__ __nv_bfloat16 g_wihhi[(size_t)PM * G3 * DF];
__device__ __nv_bfloat16 g_wihlo[(size_t)PM * G3 * DF];
__device__ __nv_bfloat16 g_whhhi[(size_t)PM * G3 * DF];
__device__ __nv_bfloat16 g_whhlo[(size_t)PM * G3 * DF];
__device__ __nv_bfloat16 g_hhi0[(size_t)PM * EE * DF];
__device__ __nv_bfloat16 g_hlo0[(size_t)PM * EE * DF];
__device__ __nv_bfloat16 g_hhi1[(size_t)PM * EE * DF];
__device__ __nv_bfloat16 g_hlo1[(size_t)PM * EE * DF];

// fast transcendentals (rel err ~2^-21)
__device__ __forceinline__ float fsig(float x) {
    return __fdividef(1.0f, 1.0f + __expf(-x));
}
__device__ __forceinline__ float ftanh_(float x) {
    return 1.0f - __fdividef(2.0f, __expf(2.0f * x) + 1.0f);
}

__device__ __forceinline__ uint32_t smem_u32(const void* p) {
    uint32_t a;
    asm("{ .reg .u64 t; cvta.to.shared.u64 t, %1; cvt.u32.u64 %0, t; }" : "=r"(a) : "l"(p));
    return a;
}

// ---- baseline-PTX tensor core + async copy (sm_80 features only) ----
__device__ __forceinline__ void ldsm4(uint32_t* r, uint32_t addr) {
    asm volatile("ldmatrix.sync.aligned.m8n8.x4.shared.b16 {%0,%1,%2,%3}, [%4];"
                 : "=r"(r[0]), "=r"(r[1]), "=r"(r[2]), "=r"(r[3]) : "r"(addr));
}
__device__ __forceinline__ void mma_bf16(float* c, const uint32_t* a, const uint32_t* b) {
    asm volatile(
        "mma.sync.aligned.m16n8k16.row.col.f32.bf16.bf16.f32 "
        "{%0,%1,%2,%3}, {%4,%5,%6,%7}, {%8,%9}, {%0,%1,%2,%3};"
        : "+f"(c[0]), "+f"(c[1]), "+f"(c[2]), "+f"(c[3])
        : "r"(a[0]), "r"(a[1]), "r"(a[2]), "r"(a[3]), "r"(b[0]), "r"(b[1]));
}
__device__ __forceinline__ void cpa16(uint32_t saddr, const void* g) {
    asm volatile("cp.async.cg.shared.global [%0], [%1], 16;" :: "r"(saddr), "l"(g));
}
#define CP_COMMIT()  asm volatile("cp.async.commit_group;" ::: "memory")
#define CP_WAIT(n)   asm volatile("cp.async.wait_group %0;" :: "n"(n) : "memory")

#define AS 40   // smem row stride in bf16 (32 + 8 pad; rows 16B aligned)

// ======== plain tensor-core GEMM (used for gi precompute) ========
// C[M,768] = A[M,256] @ W[768,256]^T + bias. CTA 128x128, BK=32, 2-stage.
#define STG 10240
#define OFF_AHI 0
#define OFF_ALO 20480
#define OFF_BHI 40960
#define OFF_BLO 61440
#define GEMM_SMEM 81920

__global__ __launch_bounds__(256, 2) void tc_gemm(
    const __nv_bfloat16* __restrict__ Ahi, const __nv_bfloat16* __restrict__ Alo,
    size_t aPstride,
    const __nv_bfloat16* __restrict__ Whi, const __nv_bfloat16* __restrict__ Wlo,
    const float* __restrict__ biasBase,
    float* __restrict__ Cbase, size_t cPstride, int M)
{
    extern __shared__ __align__(16) char sm[];
    uint32_t sb = smem_u32(sm);

    int tid = threadIdx.x, wid = tid >> 5, lane = tid & 31;
    int p = blockIdx.z, mt = blockIdx.x, nb = blockIdx.y;

    const __nv_bfloat16* Ah = Ahi + (size_t)p * aPstride;
    const __nv_bfloat16* Al = Alo + (size_t)p * aPstride;
    const __nv_bfloat16* Wh = Whi + (size_t)p * G3 * DF;
    const __nv_bfloat16* Wl = Wlo + (size_t)p * G3 * DF;
    const float* bias = biasBase + (size_t)p * G3;
    float* C = Cbase + (size_t)p * cPstride;

    int Mm1 = M - 1;
    int wm = (wid >> 1) * 32;
    int wn = (wid & 1) * 64;

    float acc[2][8][4];
#pragma unroll
    for (int mi = 0; mi < 2; mi++)
#pragma unroll
        for (int ni = 0; ni < 8; ni++)
#pragma unroll
            for (int r = 0; r < 4; r++) acc[mi][ni][r] = 0.0f;

    int ldrow0 = tid >> 2;
    int ldk8   = (tid & 3) * 8;
    int arow0 = mt * 128 + ldrow0;      if (arow0 > Mm1) arow0 = Mm1;
    int arow1 = mt * 128 + ldrow0 + 64; if (arow1 > Mm1) arow1 = Mm1;
    int brow0 = nb * 128 + ldrow0;
    int brow1 = nb * 128 + ldrow0 + 64;
    uint32_t so0 = (uint32_t)(ldrow0 * AS + ldk8) * 2u;
    uint32_t so1 = (uint32_t)((ldrow0 + 64) * AS + ldk8) * 2u;

#define LOAD_STAGE(stg, k0) do {                                              \
    uint32_t _s = (uint32_t)(stg) * STG;                                      \
    size_t _k = (size_t)(k0) + ldk8;                                          \
    cpa16(sb + OFF_AHI + _s + so0, Ah + (size_t)arow0 * DF + _k);             \
    cpa16(sb + OFF_AHI + _s + so1, Ah + (size_t)arow1 * DF + _k);             \
    cpa16(sb + OFF_ALO + _s + so0, Al + (size_t)arow0 * DF + _k);             \
    cpa16(sb + OFF_ALO + _s + so1, Al + (size_t)arow1 * DF + _k);             \
    cpa16(sb + OFF_BHI + _s + so0, Wh + (size_t)brow0 * DF + _k);             \
    cpa16(sb + OFF_BHI + _s + so1, Wh + (size_t)brow1 * DF + _k);             \
    cpa16(sb + OFF_BLO + _s + so0, Wl + (size_t)brow0 * DF + _k);             \
    cpa16(sb + OFF_BLO + _s + so1, Wl + (size_t)brow1 * DF + _k);             \
    CP_COMMIT();                                                              \
} while (0)

    int sub = lane >> 3, lr = lane & 7;

    LOAD_STAGE(0, 0);

    for (int ks = 0; ks < 8; ks++) {
        if (ks < 7) { LOAD_STAGE((ks + 1) & 1, (ks + 1) * 32); CP_WAIT(1); }
        else        { CP_WAIT(0); }
        __syncthreads();

        uint32_t st = (uint32_t)(ks & 1) * STG;
        uint32_t aHi = sb + OFF_AHI + st, aLo = sb + OFF_ALO + st;
        uint32_t bHi = sb + OFF_BHI + st, bLo = sb + OFF_BLO + st;

#pragma unroll
        for (int kh = 0; kh < 2; kh++) {
            uint32_t ah[2][4], al[2][4];
            int kcA = kh * 16 + (sub >> 1) * 8;
#pragma unroll
            for (int mi = 0; mi < 2; mi++) {
                uint32_t off = (uint32_t)((wm + mi * 16 + (sub & 1) * 8 + lr) * AS + kcA) * 2u;
                ldsm4(ah[mi], aHi + off);
                ldsm4(al[mi], aLo + off);
            }
            int brow_f = wn + (sub >> 1) * 8 + lr;
            int bcol_f = kh * 16 + (sub & 1) * 8;
#pragma unroll
            for (int nip = 0; nip < 4; nip++) {
                uint32_t off = (uint32_t)((brow_f + nip * 16) * AS + bcol_f) * 2u;
                uint32_t bh[4], bl[4];
                ldsm4(bh, bHi + off);
                ldsm4(bl, bLo + off);
#pragma unroll
                for (int mi = 0; mi < 2; mi++) {
                    mma_bf16(acc[mi][nip * 2 + 0], ah[mi], bh + 0);
                    mma_bf16(acc[mi][nip * 2 + 0], ah[mi], bl + 0);
                    mma_bf16(acc[mi][nip * 2 + 0], al[mi], bh + 0);
                    mma_bf16(acc[mi][nip * 2 + 1], ah[mi], bh + 2);
                    mma_bf16(acc[mi][nip * 2 + 1], ah[mi], bl + 2);
                    mma_bf16(acc[mi][nip * 2 + 1], al[mi], bh + 2);
                }
            }
        }
        __syncthreads();
    }

    int gRow = lane >> 2;
    int pCol = (lane & 3) * 2;
#pragma unroll
    for (int mi = 0; mi < 2; mi++) {
        int r0 = mt * 128 + wm + mi * 16 + gRow;
#pragma unroll
        for (int ni = 0; ni < 8; ni++) {
            int col = nb * 128 + wn + ni * 8 + pCol;
            float2 b2 = *(const float2*)(bias + col);
            if (r0 < M) {
                float2 o0 = make_float2(acc[mi][ni][0] + b2.x, acc[mi][ni][1] + b2.y);
                *(float2*)(C + (size_t)r0 * G3 + col) = o0;
            }
            if (r0 + 8 < M) {
                float2 o1 = make_float2(acc[mi][ni][2] + b2.x, acc[mi][ni][3] + b2.y);
                *(float2*)(C + (size_t)(r0 + 8) * G3 + col) = o1;
            }
        }
    }
}
#undef LOAD_STAGE

// ======== fused recurrent GEMM + GRU gate epilogue (ping-pong buffers) ========
// CTA: 64 edge-rows x (64 dims x 3 gates = 192 cols).
// Reads h_prev (bf16 hi/lo + fp32) from the PREV buffer, writes h to the CUR
// buffer — no same-launch read/write overlap.
#define F_AST   5120              // A stage bytes: 64*40*2
#define F_BST  15360              // B stage bytes: 192*40*2
#define F_AHI  0
#define F_ALO  (2 * F_AST)
#define F_BHI  (4 * F_AST)
#define F_BLO  (4 * F_AST + 2 * F_BST)
#define F_NODES (4 * F_AST + 4 * F_BST)
#define FUSED_SMEM (F_NODES + 256)

__global__ __launch_bounds__(256, 2) void tc_gru_fused(
    const __nv_bfloat16* __restrict__ Hhi, const __nv_bfloat16* __restrict__ Hlo,
    const float* __restrict__ Hprev,                   // fp32 h_{l-1}
    const __nv_bfloat16* __restrict__ Whi, const __nv_bfloat16* __restrict__ Wlo,
    const float* __restrict__ b_hh,
    const float* __restrict__ gi,
    const int* __restrict__ emi, int l, int last,
    float* __restrict__ Hout,                          // fp32 h_l
    __nv_bfloat16* __restrict__ HhiOut, __nv_bfloat16* __restrict__ HloOut)
{
    extern __shared__ __align__(16) char sm[];
    uint32_t sb = smem_u32(sm);
    int* snodes = (int*)(sm + F_NODES);

    int tid = threadIdx.x, wid = tid >> 5, lane = tid & 31;
    int mt = blockIdx.x, dc = blockIdx.y, p = blockIdx.z;
    int dim0 = dc * 64;

    if (tid < 64) {
        int e = mt * 64 + tid; if (e > EE - 1) e = EE - 1;
        snodes[tid] = emi[((size_t)p * EE + e) * LL + l];
    }

    int ldk8 = (tid & 3) * 8;
    int arl = tid >> 2;
    int ae = mt * 64 + arl; if (ae > EE - 1) ae = EE - 1;
    const __nv_bfloat16* pAh = Hhi + ((size_t)p * EE + ae) * DF + ldk8;
    const __nv_bfloat16* pAl = Hlo + ((size_t)p * EE + ae) * DF + ldk8;
    uint32_t aso = (uint32_t)(arl * AS + ldk8) * 2u;
    const __nv_bfloat16* pBh[3];
    const __nv_bfloat16* pBl[3];
    uint32_t bso[3];
#pragma unroll
    for (int i = 0; i < 3; i++) {
        int c = tid + 256 * i;
        int rB = c >> 2;
        int bk8 = (c & 3) * 8;
        int g = rB >> 6, j = rB & 63;
        int wrow = g * 256 + dim0 + j;
        pBh[i] = Whi + ((size_t)p * G3 + wrow) * DF + bk8;
        pBl[i] = Wlo + ((size_t)p * G3 + wrow) * DF + bk8;
        bso[i] = (uint32_t)(rB * AS + bk8) * 2u;
    }

#define F_LOAD(stg, k0) do {                                                  \
    uint32_t _as = sb + (uint32_t)(stg) * F_AST;                              \
    uint32_t _bs = sb + (uint32_t)(stg) * F_BST;                              \
    cpa16(_as + F_AHI + aso, pAh + (k0));                                     \
    cpa16(_as + F_ALO + aso, pAl + (k0));                                     \
    cpa16(_bs + F_BHI + bso[0], pBh[0] + (k0));                               \
    cpa16(_bs + F_BHI + bso[1], pBh[1] + (k0));                               \
    cpa16(_bs + F_BHI + bso[2], pBh[2] + (k0));                               \
    cpa16(_bs + F_BLO + bso[0], pBl[0] + (k0));                               \
    cpa16(_bs + F_BLO + bso[1], pBl[1] + (k0));                               \
    cpa16(_bs + F_BLO + bso[2], pBl[2] + (k0));                               \
    CP_COMMIT();                                                              \
} while (0)

    int wm   = (wid >> 2) * 32;
    int wn_j = (wid & 3) * 16;
    int sub = lane >> 3, lr = lane & 7;

    float acc[2][6][4];
#pragma unroll
    for (int mi = 0; mi < 2; mi++)
#pragma unroll
        for (int ni = 0; ni < 6; ni++)
#pragma unroll
            for (int r = 0; r < 4; r++) acc[mi][ni][r] = 0.0f;

    F_LOAD(0, 0);

    for (int ks = 0; ks < 8; ks++) {
        if (ks < 7) { F_LOAD((ks + 1) & 1, (ks + 1) * 32); CP_WAIT(1); }
        else        { CP_WAIT(0); }
        __syncthreads();

        uint32_t as_ = sb + (uint32_t)(ks & 1) * F_AST;
        uint32_t bs_ = sb + (uint32_t)(ks & 1) * F_BST;
        uint32_t aHi = as_ + F_AHI, aLo = as_ + F_ALO;
        uint32_t bHi = bs_ + F_BHI, bLo = bs_ + F_BLO;

#pragma unroll
        for (int kh = 0; kh < 2; kh++) {
            uint32_t ah[2][4], al[2][4];
            int kcA = kh * 16 + (sub >> 1) * 8;
#pragma unroll
            for (int mi = 0; mi < 2; mi++) {
                uint32_t off = (uint32_t)((wm + mi * 16 + (sub & 1) * 8 + lr) * AS + kcA) * 2u;
                ldsm4(ah[mi], aHi + off);
                ldsm4(al[mi], aLo + off);
            }
            int brow_f = wn_j + (sub >> 1) * 8 + lr;
            int bcol_f = kh * 16 + (sub & 1) * 8;
#pragma unroll
            for (int g = 0; g < 3; g++) {
                uint32_t off = (uint32_t)((g * 64 + brow_f) * AS + bcol_f) * 2u;
                uint32_t bh[4], bl[4];
                ldsm4(bh, bHi + off);
                ldsm4(bl, bLo + off);
#pragma unroll
                for (int mi = 0; mi < 2; mi++) {
                    mma_bf16(acc[mi][g * 2 + 0], ah[mi], bh + 0);
                    mma_bf16(acc[mi][g * 2 + 0], ah[mi], bl + 0);
                    mma_bf16(acc[mi][g * 2 + 0], al[mi], bh + 0);
                    mma_bf16(acc[mi][g * 2 + 1], ah[mi], bh + 2);
                    mma_bf16(acc[mi][g * 2 + 1], ah[mi], bl + 2);
                    mma_bf16(acc[mi][g * 2 + 1], al[mi], bh + 2);
                }
            }
        }
        __syncthreads();
    }

    // ---- fused GRU epilogue ----
    int gRow = lane >> 2;
    int pCol = (lane & 3) * 2;
    const float* bhp = b_hh + (size_t)p * G3;

#pragma unroll
    for (int mi = 0; mi < 2; mi++) {
#pragma unroll
        for (int rr = 0; rr < 2; rr++) {
            int row_l = wm + mi * 16 + rr * 8 + gRow;     // 0..63
            int e = mt * 64 + row_l;
            bool ok = (e < EE);
            int ec = ok ? e : (EE - 1);
            int node = snodes[row_l];
            const float* gib = gi + ((size_t)p * NN + node) * G3;
            size_t hb = ((size_t)p * EE + ec) * DF;
#pragma unroll
            for (int half = 0; half < 2; half++) {
                int j = dim0 + wn_j + half * 8 + pCol;
                float2 gir = *(const float2*)(gib + j);
                float2 giz = *(const float2*)(gib + 256 + j);
                float2 gin = *(const float2*)(gib + 512 + j);
                float2 bhr = *(const float2*)(bhp + j);
                float2 bhz = *(const float2*)(bhp + 256 + j);
                float2 bhn = *(const float2*)(bhp + 512 + j);
                float2 hp  = *(const float2*)(Hprev + hb + j);

                int ri = rr * 2;
                float r0 = fsig(gir.x + acc[mi][0 + half][ri]     + bhr.x);
                float r1 = fsig(gir.y + acc[mi][0 + half][ri + 1] + bhr.y);
                float z0 = fsig(giz.x + acc[mi][2 + half][ri]     + bhz.x);
                float z1 = fsig(giz.y + acc[mi][2 + half][ri + 1] + bhz.y);
                float n0 = ftanh_(gin.x + r0 * (acc[mi][4 + half][ri]     + bhn.x));
                float n1 = ftanh_(gin.y + r1 * (acc[mi][4 + half][ri + 1] + bhn.y));
                float h0 = (1.0f - z0) * n0 + z0 * hp.x;
                float h1 = (1.0f - z1) * n1 + z1 * hp.y;

                if (ok) {
                    *(float2*)(Hout + hb + j) = make_float2(h0, h1);
                    if (!last) {
                        __nv_bfloat16 b0 = __float2bfloat16(h0);
                        __nv_bfloat16 b1 = __float2bfloat16(h1);
                        __nv_bfloat162 hi2, lo2;
                        hi2.x = b0; hi2.y = b1;
                        lo2.x = __float2bfloat16(h0 - __bfloat162float(b0));
                        lo2.y = __float2bfloat16(h1 - __bfloat162float(b1));
                        *(__nv_bfloat162*)(HhiOut + hb + j) = hi2;
                        *(__nv_bfloat162*)(HloOut + hb + j) = lo2;
                    }
                }
            }
        }
    }
}
#undef F_LOAD

// ---------------- fp32 -> bf16 (hi, lo) split ----------------
__global__ void split_kernel(const float* __restrict__ src,
                             __nv_bfloat16* __restrict__ hi,
                             __nv_bfloat16* __restrict__ lo, size_t n) {
    size_t i = (size_t)blockIdx.x * blockDim.x + threadIdx.x;
    if (i >= n) return;
    float x = src[i];
    __nv_bfloat16 h = __float2bfloat16(x);
    hi[i] = h;
    lo[i] = __float2bfloat16(x - __bfloat162float(h));
}

__global__ void zero_kernel() {
    size_t i = (size_t)blockIdx.x * blockDim.x + threadIdx.x;
    size_t total = (size_t)PM * NN * DF;
    if (i < total) g_hout[i] = 0.0f;
    if (i < PM) g_s[i] = 0.0f;
}

// ---------------- ft = l2norm over heads ----------------
__global__ void ft_norm_kernel(const float* __restrict__ feat) {
    int t = blockIdx.x * blockDim.x + threadIdx.x;
    if (t >= NN * DD) return;
    int n = t / DD, d = t % DD;
    const float* f = feat + (size_t)n * DF + d;
    float v[HH];
    float s = 0.0f;
#pragma unroll
    for (int h = 0; h < HH; h++) { v[h] = f[h * DD]; s += v[h] * v[h]; }
    float inv = __fdividef(1.0f, fmaxf(sqrtf(s), 1e-12f));
    float* o = g_ft + (size_t)n * DF + d;
#pragma unroll
    for (int h = 0; h < HH; h++) o[h * DD] = v[h] * inv;
}

// ---------------- GRU step 0 (h=0 so gh = b_hh); writes buffer 0 ----------------
__global__ void gru_step0(const int* __restrict__ emi, const float* __restrict__ b_hh) {
    size_t i = (size_t)blockIdx.x * blockDim.x + threadIdx.x;
    size_t total = (size_t)PM * EE * DF;
    if (i >= total) return;
    int k = (int)(i & 255);
    size_t pe = i >> 8;
    int p = (int)(pe / EE);
    int node = emi[pe * LL + 0];
    const float* gi = g_gi + ((size_t)p * NN + node) * G3;
    const float* bh = b_hh + (size_t)p * G3;
    float r  = fsig(gi[k]       + bh[k]);
    float z  = fsig(gi[k + 256] + bh[k + 256]);
    float nv = ftanh_(gi[k + 512] + r * bh[k + 512]);
    float hn = (1.0f - z) * nv;
    g_h0[i] = hn;
    __nv_bfloat16 hb = __float2bfloat16(hn);
    g_hhi0[i] = hb;
    g_hlo0[i] = __float2bfloat16(hn - __bfloat162float(hb));
}

// ---------------- edge attention + segment sum ----------------
__global__ __launch_bounds__(256) void edge_attn_kernel(const int* __restrict__ edst,
                                                        const float* __restrict__ hfin) {
    int pe = blockIdx.x;
    int p = pe / EE;
    int k = threadIdx.x;
    int h = k >> 5, d = k & 31;

    float v = hfin[(size_t)pe * DF + k];

    __shared__ float sv[DF];
    __shared__ float sinvn[DD];
    __shared__ float ssim[HH];
    __shared__ float sexp[HH];
    __shared__ float sinvden;

    sv[k] = v * v;
    __syncthreads();
    if (k < DD) {
        float s = 0.0f;
#pragma unroll
        for (int hh = 0; hh < HH; hh++) s += sv[hh * DD + k];
        sinvn[k] = __fdividef(1.0f, fmaxf(sqrtf(s), 1e-12f));
    }
    __syncthreads();

    float eft = v * sinvn[d];

    int dst = edst[pe];
    float ftv = g_ft[(size_t)dst * DF + k];
    float prod = eft * ftv;
#pragma unroll
    for (int off = 16; off > 0; off >>= 1)
        prod += __shfl_down_sync(0xFFFFFFFFu, prod, off);
    if ((k & 31) == 0) ssim[h] = prod;
    __syncthreads();

    if (k < HH) {
        float mx = ssim[0];
#pragma unroll
        for (int i = 1; i < HH; i++) mx = fmaxf(mx, ssim[i]);
        sexp[k] = __expf(ssim[k] - mx);
    }
    __syncthreads();
    if (k == 0) {
        float den = 0.0f;
#pragma unroll
        for (int i = 0; i < HH; i++) den += sexp[i];
        sinvden = __fdividef(1.0f, den);
    }
    __syncthreads();

    float a = sexp[h] * sinvden;
    atomicAdd(&g_hout[((size_t)p * NN + dst) * DF + k], eft * a);
}

// ---------------- semantic attention scores ----------------
__global__ __launch_bounds__(256) void semantic_kernel(const float* __restrict__ fc1,
                                                       const float* __restrict__ fc2) {
    __shared__ float s1[DD * DD];
    __shared__ float s2[HH * DD];
    __shared__ float red[256];
    int tid = threadIdx.x;
    for (int i = tid; i < DD * DD; i += 256) s1[i] = fc1[i];
    if (tid < HH * DD) s2[tid] = fc2[tid];
    __syncthreads();

    int g = blockIdx.x * 256 + tid;
    int h = g % HH;
    int pn = g / HH;
    const float* hvp = g_hout + (size_t)pn * DF + h * DD;
    float hv[DD];
#pragma unroll
    for (int i = 0; i < 8; i++) {
        float4 v4 = *(const float4*)(hvp + i * 4);
        hv[i * 4 + 0] = v4.x; hv[i * 4 + 1] = v4.y;
        hv[i * 4 + 2] = v4.z; hv[i * 4 + 3] = v4.w;
    }
    float acc = 0.0f;
    for (int e = 0; e < DD; e++) {
        float s = 0.0f;
#pragma unroll
        for (int d = 0; d < DD; d++) s += hv[d] * s1[e * DD + d];
        acc += ftanh_(s) * s2[h * DD + e];
    }

    red[tid] = acc;
    __syncthreads();
    for (int s = 128; s > 0; s >>= 1) {
        if (tid < s) red[tid] += red[tid + s];
        __syncthreads();
    }
    if (tid == 0) {
        int p = (blockIdx.x * 256) / (NN * HH);
        atomicAdd(&g_s[p], red[0]);
    }
}

__global__ void beta_kernel() {
    if (threadIdx.x == 0 && blockIdx.x == 0) {
        float s[PM];
        float mx = -1e30f;
#pragma unroll
        for (int p = 0; p < PM; p++) { s[p] = g_s[p] / (float)NN; mx = fmaxf(mx, s[p]); }
        float den = 0.0f;
#pragma unroll
        for (int p = 0; p < PM; p++) { s[p] = expf(s[p] - mx); den += s[p]; }
#pragma unroll
        for (int p = 0; p < PM; p++) g_beta[p] = s[p] / den;
    }
}

__global__ void output_kernel(float* __restrict__ out) {
    size_t i = (size_t)blockIdx.x * blockDim.x + threadIdx.x;
    const size_t total = (size_t)NN * DF;
    if (i >= total) return;
    out[i] = g_beta[0] * g_hout[i]
           + g_beta[1] * g_hout[total + i]
           + g_beta[2] * g_hout[2 * total + i];
}

// ---------------- launch ----------------
extern "C" void kernel_launch(void* const* d_in, const int* in_sizes, int n_in,
                              void* d_out, int out_size) {
    // bind inputs by SIZE
    int idx_feat = -1, idx_fc1 = -1, idx_fc2 = -1, idx_emi = -1, idx_edst = -1;
    int idx_wA = -1, idx_wB = -1, idx_bA = -1, idx_bB = -1;
    for (int i = 0; i < n_in; i++) {
        int s = in_sizes[i];
        if      (s == NN * DF)           idx_feat = i;
        else if (s == PM * G3 * DF)      { if (idx_wA < 0) idx_wA = i; else idx_wB = i; }
        else if (s == PM * G3)           { if (idx_bA < 0) idx_bA = i; else idx_bB = i; }
        else if (s == DD * DD)           idx_fc1 = i;
        else if (s == HH * DD)           idx_fc2 = i;
        else if (s == PM * EE * LL)      idx_emi = i;
        else if (s == PM * EE)           idx_edst = i;
    }
    bool hh_first = (idx_edst >= 0 && idx_feat >= 0 && idx_edst < idx_feat);
    int idx_wih = hh_first ? idx_wB : idx_wA;
    int idx_whh = hh_first ? idx_wA : idx_wB;
    int idx_bih = hh_first ? idx_bB : idx_bA;
    int idx_bhh = hh_first ? idx_bA : idx_bB;

    const float* features = (const float*)d_in[idx_feat];
    const float* w_ih     = (const float*)d_in[idx_wih];
    const float* w_hh     = (const float*)d_in[idx_whh];
    const float* b_ih     = (const float*)d_in[idx_bih];
    const float* b_hh     = (const float*)d_in[idx_bhh];
    const float* fc1      = (const float*)d_in[idx_fc1];
    const float* fc2      = (const float*)d_in[idx_fc2];
    const int*   emi      = (const int*)d_in[idx_emi];
    const int*   edst     = (const int*)d_in[idx_edst];
    float* out = (float*)d_out;

    // device addresses of __device__ scratch (NOT host shadow symbols!)
    float *p_gi, *p_h0, *p_h1;
    __nv_bfloat16 *p_fhi, *p_flo, *p_wihhi, *p_wihlo, *p_whhhi, *p_whhlo;
    __nv_bfloat16 *p_hhi0, *p_hlo0, *p_hhi1, *p_hlo1;
    cudaGetSymbolAddress((void**)&p_gi,    g_gi);
    cudaGetSymbolAddress((void**)&p_h0,    g_h0);
    cudaGetSymbolAddress((void**)&p_h1,    g_h1);
    cudaGetSymbolAddress((void**)&p_fhi,   g_fhi);
    cudaGetSymbolAddress((void**)&p_flo,   g_flo);
    cudaGetSymbolAddress((void**)&p_wihhi, g_wihhi);
    cudaGetSymbolAddress((void**)&p_wihlo, g_wihlo);
    cudaGetSymbolAddress((void**)&p_whhhi, g_whhhi);
    cudaGetSymbolAddress((void**)&p_whhlo, g_whhlo);
    cudaGetSymbolAddress((void**)&p_hhi0,  g_hhi0);
    cudaGetSymbolAddress((void**)&p_hlo0,  g_hlo0);
    cudaGetSymbolAddress((void**)&p_hhi1,  g_hhi1);
    cudaGetSymbolAddress((void**)&p_hlo1,  g_hlo1);

    float* hbuf[2] = {p_h0, p_h1};
    __nv_bfloat16* hhib[2] = {p_hhi0, p_hhi1};
    __nv_bfloat16* hlob[2] = {p_hlo0, p_hlo1};

    cudaFuncSetAttribute(tc_gemm, cudaFuncAttributeMaxDynamicSharedMemorySize, GEMM_SMEM);
    cudaFuncSetAttribute(tc_gru_fused, cudaFuncAttributeMaxDynamicSharedMemorySize, FUSED_SMEM);

    {
        size_t total = (size_t)PM * NN * DF;
        zero_kernel<<<(unsigned)((total + 255) / 256), 256>>>();
    }

    ft_norm_kernel<<<(NN * DD + 255) / 256, 256>>>(features);

    {
        size_t nf = (size_t)NN * DF;
        split_kernel<<<(unsigned)((nf + 255) / 256), 256>>>(features, p_fhi, p_flo, nf);
        size_t nw = (size_t)PM * G3 * DF;
        split_kernel<<<(unsigned)((nw + 255) / 256), 256>>>(w_ih, p_wihhi, p_wihlo, nw);
        split_kernel<<<(unsigned)((nw + 255) / 256), 256>>>(w_hh, p_whhhi, p_whhlo, nw);
    }

    // gi[p] = features @ w_ih[p]^T + b_ih[p]
    {
        dim3 grid((NN + 127) / 128, 6, PM);
        tc_gemm<<<grid, 256, GEMM_SMEM>>>(p_fhi, p_flo, 0,
                                          p_wihhi, p_wihlo, b_ih,
                                          p_gi, (size_t)NN * G3, NN);
    }

    size_t gateTotal = (size_t)PM * EE * DF;
    unsigned gateBlocks = (unsigned)((gateTotal + 255) / 256);

    gru_step0<<<gateBlocks, 256>>>(emi, b_hh);   // writes buffer 0

    // fused recurrent GEMM + gate epilogue, ping-pong: l reads (l-1)&1, writes l&1
    {
        dim3 fgrid((EE + 63) / 64, 4, PM);
        for (int l = 1; l < LL; l++) {
            int rb = (l - 1) & 1, wb = l & 1;
            tc_gru_fused<<<fgrid, 256, FUSED_SMEM>>>(hhib[rb], hlob[rb], hbuf[rb],
                                                     p_whhhi, p_whhlo,
                                                     b_hh, p_gi, emi, l,
                                                     (l == LL - 1) ? 1 : 0,
                                                     hbuf[wb], hhib[wb], hlob[wb]);
        }
    }

    // final hidden lives in buffer (LL-1)&1 = 1
    edge_attn_kernel<<<PM * EE, 256>>>(edst, hbuf[(LL - 1) & 1]);

    semantic_kernel<<<(PM * NN * HH) / 256, 256>>>(fc1, fc2);
    beta_kernel<<<1, 32>>>();
    output_kernel<<<(unsigned)(((size_t)NN * DF + 255) / 256), 256>>>(out);
}

// round 17
// speedup vs baseline: 4.3995x; 1.6515x over previous
#include <cuda_runtime.h>
#include <cuda_fp16.h>
#include <math.h>
#include <stdint.h>

// Problem constants
#define NN 20000      // nodes
#define DF 256        // feature dim = H*D
#define PM 3          // metapaths
#define EE 60000      // edges per metapath
#define LL 4          // seq len
#define HH 8          // heads
#define DD 32         // head dim
#define G3 768        // 3 * DF (gate dim)

// ---------------- scratch (device globals; no allocation) ----------------
__device__ float g_ft  [(size_t)NN * DF];
__device__ float g_gi  [(size_t)PM * NN * G3];
// ping-pong hidden state (avoids same-launch read/write race in fused GRU)
__device__ float g_h0  [(size_t)PM * EE * DF];
__device__ float g_h1  [(size_t)PM * EE * DF];
__device__ float g_hout[(size_t)PM * NN * DF];
__device__ float g_s   [PM];
__device__ float g_beta[PM];

// fp16 operands for tensor-core GEMMs (single-pass fp16, fp32 accumulate)
__device__ __half g_f16  [(size_t)NN * DF];
__device__ __half g_wih16[(size_t)PM * G3 * DF];
__device__ __half g_whh16[(size_t)PM * G3 * DF];
__device__ __half g_h16_0[(size_t)PM * EE * DF];
__device__ __half g_h16_1[(size_t)PM * EE * DF];

// fast transcendentals (rel err ~2^-21)
__device__ __forceinline__ float fsig(float x) {
    return __fdividef(1.0f, 1.0f + __expf(-x));
}
__device__ __forceinline__ float ftanh_(float x) {
    return 1.0f - __fdividef(2.0f, __expf(2.0f * x) + 1.0f);
}

__device__ __forceinline__ uint32_t smem_u32(const void* p) {
    uint32_t a;
    asm("{ .reg .u64 t; cvta.to.shared.u64 t, %1; cvt.u32.u64 %0, t; }" : "=r"(a) : "l"(p));
    return a;
}

// ---- baseline-PTX tensor core + async copy (sm_80 features only) ----
__device__ __forceinline__ void ldsm4(uint32_t* r, uint32_t addr) {
    asm volatile("ldmatrix.sync.aligned.m8n8.x4.shared.b16 {%0,%1,%2,%3}, [%4];"
                 : "=r"(r[0]), "=r"(r[1]), "=r"(r[2]), "=r"(r[3]) : "r"(addr));
}
__device__ __forceinline__ void mma16(float* c, const uint32_t* a, const uint32_t* b) {
    asm volatile(
        "mma.sync.aligned.m16n8k16.row.col.f32.f16.f16.f32 "
        "{%0,%1,%2,%3}, {%4,%5,%6,%7}, {%8,%9}, {%0,%1,%2,%3};"
        : "+f"(c[0]), "+f"(c[1]), "+f"(c[2]), "+f"(c[3])
        : "r"(a[0]), "r"(a[1]), "r"(a[2]), "r"(a[3]), "r"(b[0]), "r"(b[1]));
}
__device__ __forceinline__ void cpa16(uint32_t saddr, const void* g) {
    asm volatile("cp.async.cg.shared.global [%0], [%1], 16;" :: "r"(saddr), "l"(g));
}
#define CP_COMMIT()  asm volatile("cp.async.commit_group;" ::: "memory")
#define CP_WAIT(n)   asm volatile("cp.async.wait_group %0;" :: "n"(n) : "memory")

#define AS 40   // smem row stride in halfs (32 + 8 pad; rows 16B aligned)

// ======== tensor-core GEMM (gi precompute): C[M,768] = A@W^T + bias ========
// single-pass fp16, fp32 acc. CTA 128x128, BK=32, 2-stage cp.async pipeline.
#define STG 10240                 // one stage of one operand: 128*40*2 bytes
#define OFF_A 0
#define OFF_B 20480
#define GEMM_SMEM 40960

__global__ __launch_bounds__(256, 2) void tc_gemm(
    const __half* __restrict__ Aq, size_t aPstride,
    const __half* __restrict__ Wq,
    const float* __restrict__ biasBase,
    float* __restrict__ Cbase, size_t cPstride, int M)
{
    extern __shared__ __align__(16) char sm[];
    uint32_t sb = smem_u32(sm);

    int tid = threadIdx.x, wid = tid >> 5, lane = tid & 31;
    int p = blockIdx.z, mt = blockIdx.x, nb = blockIdx.y;

    const __half* A = Aq + (size_t)p * aPstride;
    const __half* W = Wq + (size_t)p * G3 * DF;
    const float* bias = biasBase + (size_t)p * G3;
    float* C = Cbase + (size_t)p * cPstride;

    int Mm1 = M - 1;
    int wm = (wid >> 1) * 32;
    int wn = (wid & 1) * 64;

    float acc[2][8][4];
#pragma unroll
    for (int mi = 0; mi < 2; mi++)
#pragma unroll
        for (int ni = 0; ni < 8; ni++)
#pragma unroll
            for (int r = 0; r < 4; r++) acc[mi][ni][r] = 0.0f;

    int ldrow0 = tid >> 2;
    int ldk8   = (tid & 3) * 8;
    int arow0 = mt * 128 + ldrow0;      if (arow0 > Mm1) arow0 = Mm1;
    int arow1 = mt * 128 + ldrow0 + 64; if (arow1 > Mm1) arow1 = Mm1;
    int brow0 = nb * 128 + ldrow0;
    int brow1 = nb * 128 + ldrow0 + 64;
    uint32_t so0 = (uint32_t)(ldrow0 * AS + ldk8) * 2u;
    uint32_t so1 = (uint32_t)((ldrow0 + 64) * AS + ldk8) * 2u;

#define LOAD_STAGE(stg, k0) do {                                              \
    uint32_t _s = (uint32_t)(stg) * STG;                                      \
    size_t _k = (size_t)(k0) + ldk8;                                          \
    cpa16(sb + OFF_A + _s + so0, A + (size_t)arow0 * DF + _k);                \
    cpa16(sb + OFF_A + _s + so1, A + (size_t)arow1 * DF + _k);                \
    cpa16(sb + OFF_B + _s + so0, W + (size_t)brow0 * DF + _k);                \
    cpa16(sb + OFF_B + _s + so1, W + (size_t)brow1 * DF + _k);                \
    CP_COMMIT();                                                              \
} while (0)

    int sub = lane >> 3, lr = lane & 7;

    LOAD_STAGE(0, 0);

    for (int ks = 0; ks < 8; ks++) {
        if (ks < 7) { LOAD_STAGE((ks + 1) & 1, (ks + 1) * 32); CP_WAIT(1); }
        else        { CP_WAIT(0); }
        __syncthreads();

        uint32_t st = (uint32_t)(ks & 1) * STG;
        uint32_t aS = sb + OFF_A + st, bS = sb + OFF_B + st;

#pragma unroll
        for (int kh = 0; kh < 2; kh++) {
            uint32_t a[2][4];
            int kcA = kh * 16 + (sub >> 1) * 8;
#pragma unroll
            for (int mi = 0; mi < 2; mi++) {
                uint32_t off = (uint32_t)((wm + mi * 16 + (sub & 1) * 8 + lr) * AS + kcA) * 2u;
                ldsm4(a[mi], aS + off);
            }
            int brow_f = wn + (sub >> 1) * 8 + lr;
            int bcol_f = kh * 16 + (sub & 1) * 8;
#pragma unroll
            for (int nip = 0; nip < 4; nip++) {
                uint32_t off = (uint32_t)((brow_f + nip * 16) * AS + bcol_f) * 2u;
                uint32_t b[4];
                ldsm4(b, bS + off);
#pragma unroll
                for (int mi = 0; mi < 2; mi++) {
                    mma16(acc[mi][nip * 2 + 0], a[mi], b + 0);
                    mma16(acc[mi][nip * 2 + 1], a[mi], b + 2);
                }
            }
        }
        __syncthreads();
    }

    int gRow = lane >> 2;
    int pCol = (lane & 3) * 2;
#pragma unroll
    for (int mi = 0; mi < 2; mi++) {
        int r0 = mt * 128 + wm + mi * 16 + gRow;
#pragma unroll
        for (int ni = 0; ni < 8; ni++) {
            int col = nb * 128 + wn + ni * 8 + pCol;
            float2 b2 = *(const float2*)(bias + col);
            if (r0 < M) {
                float2 o0 = make_float2(acc[mi][ni][0] + b2.x, acc[mi][ni][1] + b2.y);
                *(float2*)(C + (size_t)r0 * G3 + col) = o0;
            }
            if (r0 + 8 < M) {
                float2 o1 = make_float2(acc[mi][ni][2] + b2.x, acc[mi][ni][3] + b2.y);
                *(float2*)(C + (size_t)(r0 + 8) * G3 + col) = o1;
            }
        }
    }
}
#undef LOAD_STAGE

// ======== fused recurrent GEMM + GRU gate epilogue (ping-pong, fp16) ========
// CTA: 64 edge-rows x (64 dims x 3 gates = 192 cols).
#define F_AST   5120              // A stage bytes: 64*40*2
#define F_BST  15360              // B stage bytes: 192*40*2
#define F_B    (2 * F_AST)
#define F_NODES (2 * F_AST + 2 * F_BST)
#define FUSED_SMEM (F_NODES + 256)

__global__ __launch_bounds__(256, 2) void tc_gru_fused(
    const __half* __restrict__ H16, const float* __restrict__ Hprev,
    const __half* __restrict__ W16,
    const float* __restrict__ b_hh,
    const float* __restrict__ gi,
    const int* __restrict__ emi, int l, int last,
    float* __restrict__ Hout, __half* __restrict__ H16Out)
{
    extern __shared__ __align__(16) char sm[];
    uint32_t sb = smem_u32(sm);
    int* snodes = (int*)(sm + F_NODES);

    int tid = threadIdx.x, wid = tid >> 5, lane = tid & 31;
    int mt = blockIdx.x, dc = blockIdx.y, p = blockIdx.z;
    int dim0 = dc * 64;

    if (tid < 64) {
        int e = mt * 64 + tid; if (e > EE - 1) e = EE - 1;
        snodes[tid] = emi[((size_t)p * EE + e) * LL + l];
    }

    int ldk8 = (tid & 3) * 8;
    int arl = tid >> 2;
    int ae = mt * 64 + arl; if (ae > EE - 1) ae = EE - 1;
    const __half* pA = H16 + ((size_t)p * EE + ae) * DF + ldk8;
    uint32_t aso = (uint32_t)(arl * AS + ldk8) * 2u;
    const __half* pB[3];
    uint32_t bso[3];
#pragma unroll
    for (int i = 0; i < 3; i++) {
        int c = tid + 256 * i;
        int rB = c >> 2;
        int bk8 = (c & 3) * 8;
        int g = rB >> 6, j = rB & 63;
        int wrow = g * 256 + dim0 + j;
        pB[i] = W16 + ((size_t)p * G3 + wrow) * DF + bk8;
        bso[i] = (uint32_t)(rB * AS + bk8) * 2u;
    }

#define F_LOAD(stg, k0) do {                                                  \
    uint32_t _as = sb + (uint32_t)(stg) * F_AST;                              \
    uint32_t _bs = sb + F_B + (uint32_t)(stg) * F_BST;                        \
    cpa16(_as + aso, pA + (k0));                                              \
    cpa16(_bs + bso[0], pB[0] + (k0));                                        \
    cpa16(_bs + bso[1], pB[1] + (k0));                                        \
    cpa16(_bs + bso[2], pB[2] + (k0));                                        \
    CP_COMMIT();                                                              \
} while (0)

    int wm   = (wid >> 2) * 32;
    int wn_j = (wid & 3) * 16;
    int sub = lane >> 3, lr = lane & 7;

    float acc[2][6][4];
#pragma unroll
    for (int mi = 0; mi < 2; mi++)
#pragma unroll
        for (int ni = 0; ni < 6; ni++)
#pragma unroll
            for (int r = 0; r < 4; r++) acc[mi][ni][r] = 0.0f;

    F_LOAD(0, 0);

    for (int ks = 0; ks < 8; ks++) {
        if (ks < 7) { F_LOAD((ks + 1) & 1, (ks + 1) * 32); CP_WAIT(1); }
        else        { CP_WAIT(0); }
        __syncthreads();

        uint32_t aS = sb + (uint32_t)(ks & 1) * F_AST;
        uint32_t bS = sb + F_B + (uint32_t)(ks & 1) * F_BST;

#pragma unroll
        for (int kh = 0; kh < 2; kh++) {
            uint32_t a[2][4];
            int kcA = kh * 16 + (sub >> 1) * 8;
#pragma unroll
            for (int mi = 0; mi < 2; mi++) {
                uint32_t off = (uint32_t)((wm + mi * 16 + (sub & 1) * 8 + lr) * AS + kcA) * 2u;
                ldsm4(a[mi], aS + off);
            }
            int brow_f = wn_j + (sub >> 1) * 8 + lr;
            int bcol_f = kh * 16 + (sub & 1) * 8;
#pragma unroll
            for (int g = 0; g < 3; g++) {
                uint32_t off = (uint32_t)((g * 64 + brow_f) * AS + bcol_f) * 2u;
                uint32_t b[4];
                ldsm4(b, bS + off);
#pragma unroll
                for (int mi = 0; mi < 2; mi++) {
                    mma16(acc[mi][g * 2 + 0], a[mi], b + 0);
                    mma16(acc[mi][g * 2 + 1], a[mi], b + 2);
                }
            }
        }
        __syncthreads();
    }

    // ---- fused GRU epilogue ----
    int gRow = lane >> 2;
    int pCol = (lane & 3) * 2;
    const float* bhp = b_hh + (size_t)p * G3;

#pragma unroll
    for (int mi = 0; mi < 2; mi++) {
#pragma unroll
        for (int rr = 0; rr < 2; rr++) {
            int row_l = wm + mi * 16 + rr * 8 + gRow;     // 0..63
            int e = mt * 64 + row_l;
            bool ok = (e < EE);
            int ec = ok ? e : (EE - 1);
            int node = snodes[row_l];
            const float* gib = gi + ((size_t)p * NN + node) * G3;
            size_t hb = ((size_t)p * EE + ec) * DF;
#pragma unroll
            for (int half = 0; half < 2; half++) {
                int j = dim0 + wn_j + half * 8 + pCol;
                float2 gir = *(const float2*)(gib + j);
                float2 giz = *(const float2*)(gib + 256 + j);
                float2 gin = *(const float2*)(gib + 512 + j);
                float2 bhr = *(const float2*)(bhp + j);
                float2 bhz = *(const float2*)(bhp + 256 + j);
                float2 bhn = *(const float2*)(bhp + 512 + j);
                float2 hp  = *(const float2*)(Hprev + hb + j);

                int ri = rr * 2;
                float r0 = fsig(gir.x + acc[mi][0 + half][ri]     + bhr.x);
                float r1 = fsig(gir.y + acc[mi][0 + half][ri + 1] + bhr.y);
                float z0 = fsig(giz.x + acc[mi][2 + half][ri]     + bhz.x);
                float z1 = fsig(giz.y + acc[mi][2 + half][ri + 1] + bhz.y);
                float n0 = ftanh_(gin.x + r0 * (acc[mi][4 + half][ri]     + bhn.x));
                float n1 = ftanh_(gin.y + r1 * (acc[mi][4 + half][ri + 1] + bhn.y));
                float h0 = (1.0f - z0) * n0 + z0 * hp.x;
                float h1 = (1.0f - z1) * n1 + z1 * hp.y;

                if (ok) {
                    *(float2*)(Hout + hb + j) = make_float2(h0, h1);
                    if (!last) {
                        *(__half2*)(H16Out + hb + j) = __floats2half2_rn(h0, h1);
                    }
                }
            }
        }
    }
}
#undef F_LOAD

// ---------------- fp32 -> fp16 convert ----------------
__global__ void cvt16_kernel(const float* __restrict__ src,
                             __half* __restrict__ dst, size_t n) {
    size_t i = (size_t)blockIdx.x * blockDim.x + threadIdx.x;
    if (i >= n) return;
    dst[i] = __float2half_rn(src[i]);
}

__global__ void zero_kernel() {
    size_t i = (size_t)blockIdx.x * blockDim.x + threadIdx.x;
    size_t total = (size_t)PM * NN * DF;
    if (i < total) g_hout[i] = 0.0f;
    if (i < PM) g_s[i] = 0.0f;
}

// ---------------- ft = l2norm over heads ----------------
__global__ void ft_norm_kernel(const float* __restrict__ feat) {
    int t = blockIdx.x * blockDim.x + threadIdx.x;
    if (t >= NN * DD) return;
    int n = t / DD, d = t % DD;
    const float* f = feat + (size_t)n * DF + d;
    float v[HH];
    float s = 0.0f;
#pragma unroll
    for (int h = 0; h < HH; h++) { v[h] = f[h * DD]; s += v[h] * v[h]; }
    float inv = __fdividef(1.0f, fmaxf(sqrtf(s), 1e-12f));
    float* o = g_ft + (size_t)n * DF + d;
#pragma unroll
    for (int h = 0; h < HH; h++) o[h * DD] = v[h] * inv;
}

// ---------------- GRU step 0 (h=0 so gh = b_hh); writes buffer 0 ----------------
__global__ void gru_step0(const int* __restrict__ emi, const float* __restrict__ b_hh) {
    size_t i = (size_t)blockIdx.x * blockDim.x + threadIdx.x;
    size_t total = (size_t)PM * EE * DF;
    if (i >= total) return;
    int k = (int)(i & 255);
    size_t pe = i >> 8;
    int p = (int)(pe / EE);
    int node = emi[pe * LL + 0];
    const float* gi = g_gi + ((size_t)p * NN + node) * G3;
    const float* bh = b_hh + (size_t)p * G3;
    float r  = fsig(gi[k]       + bh[k]);
    float z  = fsig(gi[k + 256] + bh[k + 256]);
    float nv = ftanh_(gi[k + 512] + r * bh[k + 512]);
    float hn = (1.0f - z) * nv;
    g_h0[i] = hn;
    g_h16_0[i] = __float2half_rn(hn);
}

// ---------------- edge attention + segment sum ----------------
__global__ __launch_bounds__(256) void edge_attn_kernel(const int* __restrict__ edst,
                                                        const float* __restrict__ hfin) {
    int pe = blockIdx.x;
    int p = pe / EE;
    int k = threadIdx.x;
    int h = k >> 5, d = k & 31;

    float v = hfin[(size_t)pe * DF + k];

    __shared__ float sv[DF];
    __shared__ float sinvn[DD];
    __shared__ float ssim[HH];
    __shared__ float sexp[HH];
    __shared__ float sinvden;

    sv[k] = v * v;
    __syncthreads();
    if (k < DD) {
        float s = 0.0f;
#pragma unroll
        for (int hh = 0; hh < HH; hh++) s += sv[hh * DD + k];
        sinvn[k] = __fdividef(1.0f, fmaxf(sqrtf(s), 1e-12f));
    }
    __syncthreads();

    float eft = v * sinvn[d];

    int dst = edst[pe];
    float ftv = g_ft[(size_t)dst * DF + k];
    float prod = eft * ftv;
#pragma unroll
    for (int off = 16; off > 0; off >>= 1)
        prod += __shfl_down_sync(0xFFFFFFFFu, prod, off);
    if ((k & 31) == 0) ssim[h] = prod;
    __syncthreads();

    if (k < HH) {
        float mx = ssim[0];
#pragma unroll
        for (int i = 1; i < HH; i++) mx = fmaxf(mx, ssim[i]);
        sexp[k] = __expf(ssim[k] - mx);
    }
    __syncthreads();
    if (k == 0) {
        float den = 0.0f;
#pragma unroll
        for (int i = 0; i < HH; i++) den += sexp[i];
        sinvden = __fdividef(1.0f, den);
    }
    __syncthreads();

    float a = sexp[h] * sinvden;
    atomicAdd(&g_hout[((size_t)p * NN + dst) * DF + k], eft * a);
}

// ---------------- semantic attention scores ----------------
__global__ __launch_bounds__(256) void semantic_kernel(const float* __restrict__ fc1,
                                                       const float* __restrict__ fc2) {
    __shared__ float s1[DD * DD];
    __shared__ float s2[HH * DD];
    __shared__ float red[256];
    int tid = threadIdx.x;
    for (int i = tid; i < DD * DD; i += 256) s1[i] = fc1[i];
    if (tid < HH * DD) s2[tid] = fc2[tid];
    __syncthreads();

    int g = blockIdx.x * 256 + tid;
    int h = g % HH;
    int pn = g / HH;
    const float* hvp = g_hout + (size_t)pn * DF + h * DD;
    float hv[DD];
#pragma unroll
    for (int i = 0; i < 8; i++) {
        float4 v4 = *(const float4*)(hvp + i * 4);
        hv[i * 4 + 0] = v4.x; hv[i * 4 + 1] = v4.y;
        hv[i * 4 + 2] = v4.z; hv[i * 4 + 3] = v4.w;
    }
    float acc = 0.0f;
    for (int e = 0; e < DD; e++) {
        float s = 0.0f;
#pragma unroll
        for (int d = 0; d < DD; d++) s += hv[d] * s1[e * DD + d];
        acc += ftanh_(s) * s2[h * DD + e];
    }

    red[tid] = acc;
    __syncthreads();
    for (int s = 128; s > 0; s >>= 1) {
        if (tid < s) red[tid] += red[tid + s];
        __syncthreads();
    }
    if (tid == 0) {
        int p = (blockIdx.x * 256) / (NN * HH);
        atomicAdd(&g_s[p], red[0]);
    }
}

__global__ void beta_kernel() {
    if (threadIdx.x == 0 && blockIdx.x == 0) {
        float s[PM];
        float mx = -1e30f;
#pragma unroll
        for (int p = 0; p < PM; p++) { s[p] = g_s[p] / (float)NN; mx = fmaxf(mx, s[p]); }
        float den = 0.0f;
#pragma unroll
        for (int p = 0; p < PM; p++) { s[p] = expf(s[p] - mx); den += s[p]; }
#pragma unroll
        for (int p = 0; p < PM; p++) g_beta[p] = s[p] / den;
    }
}

__global__ void output_kernel(float* __restrict__ out) {
    size_t i = (size_t)blockIdx.x * blockDim.x + threadIdx.x;
    const size_t total = (size_t)NN * DF;
    if (i >= total) return;
    out[i] = g_beta[0] * g_hout[i]
           + g_beta[1] * g_hout[total + i]
           + g_beta[2] * g_hout[2 * total + i];
}

// ---------------- launch ----------------
extern "C" void kernel_launch(void* const* d_in, const int* in_sizes, int n_in,
                              void* d_out, int out_size) {
    // bind inputs by SIZE
    int idx_feat = -1, idx_fc1 = -1, idx_fc2 = -1, idx_emi = -1, idx_edst = -1;
    int idx_wA = -1, idx_wB = -1, idx_bA = -1, idx_bB = -1;
    for (int i = 0; i < n_in; i++) {
        int s = in_sizes[i];
        if      (s == NN * DF)           idx_feat = i;
        else if (s == PM * G3 * DF)      { if (idx_wA < 0) idx_wA = i; else idx_wB = i; }
        else if (s == PM * G3)           { if (idx_bA < 0) idx_bA = i; else idx_bB = i; }
        else if (s == DD * DD)           idx_fc1 = i;
        else if (s == HH * DD)           idx_fc2 = i;
        else if (s == PM * EE * LL)      idx_emi = i;
        else if (s == PM * EE)           idx_edst = i;
    }
    bool hh_first = (idx_edst >= 0 && idx_feat >= 0 && idx_edst < idx_feat);
    int idx_wih = hh_first ? idx_wB : idx_wA;
    int idx_whh = hh_first ? idx_wA : idx_wB;
    int idx_bih = hh_first ? idx_bB : idx_bA;
    int idx_bhh = hh_first ? idx_bA : idx_bB;

    const float* features = (const float*)d_in[idx_feat];
    const float* w_ih     = (const float*)d_in[idx_wih];
    const float* w_hh     = (const float*)d_in[idx_whh];
    const float* b_ih     = (const float*)d_in[idx_bih];
    const float* b_hh     = (const float*)d_in[idx_bhh];
    const float* fc1      = (const float*)d_in[idx_fc1];
    const float* fc2      = (const float*)d_in[idx_fc2];
    const int*   emi      = (const int*)d_in[idx_emi];
    const int*   edst     = (const int*)d_in[idx_edst];
    float* out = (float*)d_out;

    // device addresses of __device__ scratch (NOT host shadow symbols!)
    float *p_gi, *p_h0, *p_h1;
    __half *p_f16, *p_wih16, *p_whh16, *p_h16_0, *p_h16_1;
    cudaGetSymbolAddress((void**)&p_gi,    g_gi);
    cudaGetSymbolAddress((void**)&p_h0,    g_h0);
    cudaGetSymbolAddress((void**)&p_h1,    g_h1);
    cudaGetSymbolAddress((void**)&p_f16,   g_f16);
    cudaGetSymbolAddress((void**)&p_wih16, g_wih16);
    cudaGetSymbolAddress((void**)&p_whh16, g_whh16);
    cudaGetSymbolAddress((void**)&p_h16_0, g_h16_0);
    cudaGetSymbolAddress((void**)&p_h16_1, g_h16_1);

    float* hbuf[2] = {p_h0, p_h1};
    __half* h16b[2] = {p_h16_0, p_h16_1};

    cudaFuncSetAttribute(tc_gemm, cudaFuncAttributeMaxDynamicSharedMemorySize, GEMM_SMEM);
    cudaFuncSetAttribute(tc_gru_fused, cudaFuncAttributeMaxDynamicSharedMemorySize, FUSED_SMEM);

    {
        size_t total = (size_t)PM * NN * DF;
        zero_kernel<<<(unsigned)((total + 255) / 256), 256>>>();
    }

    ft_norm_kernel<<<(NN * DD + 255) / 256, 256>>>(features);

    {
        size_t nf = (size_t)NN * DF;
        cvt16_kernel<<<(unsigned)((nf + 255) / 256), 256>>>(features, p_f16, nf);
        size_t nw = (size_t)PM * G3 * DF;
        cvt16_kernel<<<(unsigned)((nw + 255) / 256), 256>>>(w_ih, p_wih16, nw);
        cvt16_kernel<<<(unsigned)((nw + 255) / 256), 256>>>(w_hh, p_whh16, nw);
    }

    // gi[p] = features @ w_ih[p]^T + b_ih[p]
    {
        dim3 grid((NN + 127) / 128, 6, PM);
        tc_gemm<<<grid, 256, GEMM_SMEM>>>(p_f16, 0,
                                          p_wih16, b_ih,
                                          p_gi, (size_t)NN * G3, NN);
    }

    size_t gateTotal = (size_t)PM * EE * DF;
    unsigned gateBlocks = (unsigned)((gateTotal + 255) / 256);

    gru_step0<<<gateBlocks, 256>>>(emi, b_hh);   // writes buffer 0

    // fused recurrent GEMM + gate epilogue, ping-pong: l reads (l-1)&1, writes l&1
    {
        dim3 fgrid((EE + 63) / 64, 4, PM);
        for (int l = 1; l < LL; l++) {
            int rb = (l - 1) & 1, wb = l & 1;
            tc_gru_fused<<<fgrid, 256, FUSED_SMEM>>>(h16b[rb], hbuf[rb],
                                                     p_whh16,
                                                     b_hh, p_gi, emi, l,
                                                     (l == LL - 1) ? 1 : 0,
                                                     hbuf[wb], h16b[wb]);
        }
    }

    // final hidden lives in buffer (LL-1)&1 = 1
    edge_attn_kernel<<<PM * EE, 256>>>(edst, hbuf[(LL - 1) & 1]);

    semantic_kernel<<<(PM * NN * HH) / 256, 256>>>(fc1, fc2);
    beta_kernel<<<1, 32>>>();
    output_kernel<<<(unsigned)(((size_t)NN * DF + 255) / 256), 256>>>(out);
}